// round 14
// baseline (speedup 1.0000x reference)
#include <cuda_runtime.h>
#include <cuda_fp16.h>
#include <cstdint>

#define B_  2
#define S_  2048
#define D_  1024
#define H_  16
#define DK_ 64

typedef unsigned int u32;

// ---------------- scratch (device globals: allocation-free) ----------------
__device__ __half g_Xq[(size_t)B_ * S_ * D_];
__device__ __half g_Xk[(size_t)B_ * S_ * D_];
__device__ __half g_Xv[(size_t)B_ * S_ * D_];
__device__ __half g_Qh[(size_t)B_ * S_ * D_];
__device__ __half g_Kh[(size_t)B_ * S_ * D_];
__device__ __half g_Vt[(size_t)B_ * S_ * D_];      // V transposed [b][h][dk][S]
__device__ __half g_Oh[(size_t)B_ * S_ * D_];
__device__ __half g_Ph[(size_t)S_ * S_];
__device__ __half g_Wqt[(size_t)D_ * D_];
__device__ __half g_Wkt[(size_t)D_ * D_];
__device__ __half g_Wvt[(size_t)D_ * D_];
__device__ __half g_Wot[(size_t)D_ * D_];
__device__ __half g_S1[(size_t)B_ * H_ * S_ * S_]; // 256 MB
__device__ __half g_S2[(size_t)B_ * H_ * S_ * S_]; // 256 MB
__device__ u32    g_Mb[(size_t)B_ * S_ * S_ / 32]; // bitpacked mask (1 MB)
__device__ float2 g_RS[(size_t)B_ * H_ * S_];      // per-row (max, 1/sum)

// ---------------- asm helpers ----------------
__device__ __forceinline__ void mma16(float* c, const u32* a, const u32* b) {
    asm volatile(
        "mma.sync.aligned.m16n8k16.row.col.f32.f16.f16.f32 "
        "{%0,%1,%2,%3},{%4,%5,%6,%7},{%8,%9},{%0,%1,%2,%3};\n"
        : "+f"(c[0]), "+f"(c[1]), "+f"(c[2]), "+f"(c[3])
        : "r"(a[0]), "r"(a[1]), "r"(a[2]), "r"(a[3]), "r"(b[0]), "r"(b[1]));
}

__device__ __forceinline__ void ldsm4(u32& r0, u32& r1, u32& r2, u32& r3, u32 a) {
    asm volatile("ldmatrix.sync.aligned.m8n8.x4.shared.b16 {%0,%1,%2,%3}, [%4];"
                 : "=r"(r0), "=r"(r1), "=r"(r2), "=r"(r3) : "r"(a));
}

__device__ __forceinline__ u32 smem_u32(const void* p) {
    u32 a;
    asm("{ .reg .u64 t; cvta.to.shared.u64 t, %1; cvt.u32.u64 %0, t; }"
        : "=r"(a) : "l"(p));
    return a;
}

__device__ __forceinline__ void cpa16(u32 dst, const void* src) {
    asm volatile("cp.async.cg.shared.global [%0], [%1], 16;" :: "r"(dst), "l"(src));
}
#define CP_COMMIT() asm volatile("cp.async.commit_group;" ::: "memory")

struct HP {
    const __half* A;
    const __half* Bm;
    void*         C;
    const float*  bias;
    const u32*    mask;       // bitpacked
    const __half *A1, *A2, *Bm1, *Bm2;   // EPI5 (triple projection)
    void *C1, *C2;
    const float *bias1, *bias2;
    long lda, ldb, ldc;
    long Ab, Ah, Bb, Bh, Cb, Ch, maskB;
    float scale;
    int  K;
};

// ---------------- fp16 NT GEMM template ----------------
// EPI: 0 plain fp16, 2 maskbit?v*scale:0 fp16, 4 +bias fp32,
//      5 triple-projection (z selects operands; z==2 stores transposed V)
template<int BM, int BN, int WMN, int WNN, int EPI, int STAGES, int MINB = 1>
__global__ __launch_bounds__(256, MINB) void gemm_l(HP p) {
    static_assert(WMN * WNN == 8, "8 warps");
    constexpr int WTM  = BM / WMN;
    constexpr int WTN  = BN / WNN;
    constexpr int MT   = WTM / 16;
    constexpr int NTj  = WTN / 8;
    constexpr int STGB = (BM + BN) * 128;
    constexpr int CHK  = (BM + BN) * 8 / 256;

    extern __shared__ __align__(1024) char smem[];
    const u32 sb = smem_u32(smem);

    const int tid  = threadIdx.x;
    const int wid  = tid >> 5, lane = tid & 31;
    const int wm   = wid / WNN, wn = wid % WNN;
    const int g    = lane >> 2, tg = lane & 3;
    const int z    = blockIdx.z;
    const int b    = z / H_, h = z % H_;

    const __half *Abase, *Bbase;
    if constexpr (EPI == 5) {
        Abase = (z == 0) ? p.A : (z == 1) ? p.A1 : p.A2;
        Bbase = (z == 0) ? p.Bm : (z == 1) ? p.Bm1 : p.Bm2;
    } else {
        Abase = p.A + (long)b * p.Ab + (long)h * p.Ah;
        Bbase = p.Bm + (long)b * p.Bb + (long)h * p.Bh;
    }
    const __half* Ab = Abase + (long)blockIdx.y * BM * p.lda;
    const __half* Bb = Bbase + (long)blockIdx.x * BN * p.ldb;

    const int KT = p.K >> 6;

    int cR[CHK], cC[CHK];
#pragma unroll
    for (int i = 0; i < CHK; i++) {
        int id = tid + i * 256;
        cR[i] = id >> 3;
        cC[i] = id & 7;
    }

    auto loadStage = [&](int kt) {
        if (kt < KT) {
            const u32 s0 = sb + (kt % STAGES) * STGB;
#pragma unroll
            for (int i = 0; i < CHK; i++) {
                int r = cR[i], c = cC[i];
                if (r < BM) {
                    cpa16(s0 + r * 128 + ((c ^ (r & 7)) << 4),
                          Ab + (long)r * p.lda + kt * 64 + c * 8);
                } else {
                    int rr = r - BM;
                    cpa16(s0 + BM * 128 + rr * 128 + ((c ^ (rr & 7)) << 4),
                          Bb + (long)rr * p.ldb + kt * 64 + c * 8);
                }
            }
        }
        CP_COMMIT();
    };

    const int la = lane & 7;
    const int ksegA = (lane >> 4) & 1;
    const int ksegB = (lane >> 3) & 1;
    int aRow[MT], aSw[MT], bRow[NTj / 2], bSw[NTj / 2];
#pragma unroll
    for (int i = 0; i < MT; i++) {
        int r = wm * WTM + i * 16 + ((lane >> 3) & 1) * 8 + la;
        aRow[i] = r * 128;
        aSw[i]  = r & 7;
    }
#pragma unroll
    for (int j = 0; j < NTj / 2; j++) {
        int r = wn * WTN + j * 16 + ((lane >> 4) & 1) * 8 + la;
        bRow[j] = r * 128;
        bSw[j]  = r & 7;
    }

    float acc[MT][NTj][4];
#pragma unroll
    for (int i = 0; i < MT; i++)
#pragma unroll
        for (int j = 0; j < NTj; j++)
#pragma unroll
            for (int k = 0; k < 4; k++) acc[i][j][k] = 0.f;

#pragma unroll
    for (int s = 0; s < STAGES - 1; s++) loadStage(s);

    for (int kt = 0; kt < KT; kt++) {
        asm volatile("cp.async.wait_group %0;" :: "n"(STAGES - 2));
        __syncthreads();
        loadStage(kt + STAGES - 1);

        const u32 sA = sb + (kt % STAGES) * STGB;
        const u32 sB = sA + BM * 128;
#pragma unroll
        for (int ks = 0; ks < 4; ks++) {
            u32 af[MT][4], bf[NTj][2];
            const int ca = ks * 2 + ksegA;
            const int cb = ks * 2 + ksegB;
#pragma unroll
            for (int i = 0; i < MT; i++)
                ldsm4(af[i][0], af[i][1], af[i][2], af[i][3],
                      sA + aRow[i] + ((ca ^ aSw[i]) << 4));
#pragma unroll
            for (int j = 0; j < NTj / 2; j++)
                ldsm4(bf[2 * j][0], bf[2 * j][1], bf[2 * j + 1][0], bf[2 * j + 1][1],
                      sB + bRow[j] + ((cb ^ bSw[j]) << 4));
#pragma unroll
            for (int i = 0; i < MT; i++)
#pragma unroll
                for (int j = 0; j < NTj; j++)
                    mma16(acc[i][j], af[i], bf[j]);
        }
    }

    // ---------------- epilogue ----------------
    const long row0 = (long)blockIdx.y * BM + wm * WTM;
    const long col0 = (long)blockIdx.x * BN + wn * WTN;

#pragma unroll
    for (int i = 0; i < MT; i++) {
        const long r0 = row0 + i * 16 + g;
#pragma unroll
        for (int j = 0; j < NTj; j++) {
            const long c = col0 + j * 8 + tg * 2;
            float v0 = acc[i][j][0], v1 = acc[i][j][1];
            float v2 = acc[i][j][2], v3 = acc[i][j][3];
            if constexpr (EPI == 4) {
                float b0 = p.bias[c], b1 = p.bias[c + 1];
                v0 += b0; v1 += b1; v2 += b0; v3 += b1;
                float* C = (float*)p.C + (long)b * p.Cb + (long)h * p.Ch;
                *(float2*)(C + r0 * p.ldc + c)       = make_float2(v0, v1);
                *(float2*)(C + (r0 + 8) * p.ldc + c) = make_float2(v2, v3);
            } else if constexpr (EPI == 2) {
                const u32* mb = p.mask + (long)b * p.maskB;
                const int  wofs = (int)(c >> 5), sh = (int)(c & 31);
                u32 w0 = mb[r0 * (S_ / 32) + wofs];
                u32 w1 = mb[(r0 + 8) * (S_ / 32) + wofs];
                v0 = (w0 >> sh) & 1       ? v0 * p.scale : 0.f;
                v1 = (w0 >> (sh + 1)) & 1 ? v1 * p.scale : 0.f;
                v2 = (w1 >> sh) & 1       ? v2 * p.scale : 0.f;
                v3 = (w1 >> (sh + 1)) & 1 ? v3 * p.scale : 0.f;
                __half* C = (__half*)p.C + (long)b * p.Cb + (long)h * p.Ch;
                *(__half2*)(C + r0 * p.ldc + c)       = __floats2half2_rn(v0, v1);
                *(__half2*)(C + (r0 + 8) * p.ldc + c) = __floats2half2_rn(v2, v3);
            } else if constexpr (EPI == 5) {
                const float* bs = (z == 0) ? p.bias : (z == 1) ? p.bias1 : p.bias2;
                float b0 = bs[c], b1 = bs[c + 1];
                v0 += b0; v1 += b1; v2 += b0; v3 += b1;
                if (z == 2) {
                    __half* Ct = (__half*)p.C2;
                    const int hh = (int)(c >> 6), d = (int)(c & 63);
                    {
                        const long bb = r0 >> 11, s = r0 & (S_ - 1);
                        __half* base = Ct + ((bb * H_ + hh) * 64 + d) * (long)S_ + s;
                        base[0]  = __float2half_rn(v0);
                        base[S_] = __float2half_rn(v1);
                    }
                    {
                        const long bb = (r0 + 8) >> 11, s = (r0 + 8) & (S_ - 1);
                        __half* base = Ct + ((bb * H_ + hh) * 64 + d) * (long)S_ + s;
                        base[0]  = __float2half_rn(v2);
                        base[S_] = __float2half_rn(v3);
                    }
                } else {
                    __half* C = (__half*)(z == 0 ? p.C : p.C1);
                    *(__half2*)(C + r0 * p.ldc + c)       = __floats2half2_rn(v0, v1);
                    *(__half2*)(C + (r0 + 8) * p.ldc + c) = __floats2half2_rn(v2, v3);
                }
            } else {
                __half* C = (__half*)p.C + (long)b * p.Cb + (long)h * p.Ch;
                *(__half2*)(C + r0 * p.ldc + c)       = __floats2half2_rn(v0, v1);
                *(__half2*)(C + (r0 + 8) * p.ldc + c) = __floats2half2_rn(v2, v3);
            }
        }
    }
}

// ================ AV GEMM with fused softmax normalize (probs on the fly) ====
// Oh[128 q, 64 d] = softmax(S2) @ Vt using precomputed per-row (max, inv).
// Memory-latency-bound kernel: the exp transform (~30us chip-wide MUFU) hides
// under the cp.async pipeline, unlike the tensor-saturated prop kernel.
__global__ __launch_bounds__(256, 2) void av_fused(
    const __half* __restrict__ Sg, const __half* __restrict__ Vg,
    __half* __restrict__ Og, const u32* __restrict__ Mb,
    const float2* __restrict__ RS)
{
    constexpr int BM = 128, BN = 64, STAGES = 4;
    constexpr int STGB = (BM + BN) * 128;     // 24576
    constexpr int CHK  = 6;
    constexpr int MT = 2, NTj = 4;            // warps 4x2, warp tile 32x32
    constexpr int KT = 32;

    extern __shared__ __align__(1024) char smem[];
    __shared__ float rMax[BM], rInv[BM];
    const u32 sb = smem_u32(smem);

    const int tid  = threadIdx.x;
    const int wid  = tid >> 5, lane = tid & 31;
    const int wm   = wid >> 1, wn = wid & 1;
    const int g    = lane >> 2, tg = lane & 3;
    const int z    = blockIdx.z, b = z >> 4, h = z & 15;
    const long q0  = (long)blockIdx.y * BM;

    const __half* Ab = Sg + (long)z * S_ * S_ + q0 * S_;
    const __half* Bb = Vg + (long)z * DK_ * S_;
    const u32* Mrow  = Mb + ((long)b * S_ + q0) * (S_ / 32);

    if (tid < BM) {
        float2 s = RS[(long)z * S_ + q0 + tid];
        rMax[tid] = s.x;
        rInv[tid] = s.y;
    }

    int cR[CHK], cC[CHK];
#pragma unroll
    for (int i = 0; i < CHK; i++) {
        int id = tid + i * 256;
        cR[i] = id >> 3;
        cC[i] = id & 7;
    }
    auto loadStage = [&](int kt) {
        if (kt < KT) {
            const u32 s0 = sb + (kt & 3) * STGB;
#pragma unroll
            for (int i = 0; i < CHK; i++) {
                int r = cR[i], c = cC[i];
                if (r < BM) {
                    cpa16(s0 + r * 128 + ((c ^ (r & 7)) << 4),
                          Ab + (long)r * S_ + kt * 64 + c * 8);
                } else {
                    int rr = r - BM;
                    cpa16(s0 + BM * 128 + rr * 128 + ((c ^ (rr & 7)) << 4),
                          Bb + (long)rr * S_ + kt * 64 + c * 8);
                }
            }
        }
        CP_COMMIT();
    };

    const int la = lane & 7;
    const int ksegA = (lane >> 4) & 1;
    const int ksegB = (lane >> 3) & 1;
    int aRow[MT], aSw[MT], bRow[NTj / 2], bSw[NTj / 2];
#pragma unroll
    for (int i = 0; i < MT; i++) {
        int r = wm * 32 + i * 16 + ((lane >> 3) & 1) * 8 + la;
        aRow[i] = r * 128;
        aSw[i]  = r & 7;
    }
#pragma unroll
    for (int j = 0; j < NTj / 2; j++) {
        int r = wn * 32 + j * 16 + ((lane >> 4) & 1) * 8 + la;
        bRow[j] = r * 128;
        bSw[j]  = r & 7;
    }

    float acc[MT][NTj][4];
#pragma unroll
    for (int i = 0; i < MT; i++)
#pragma unroll
        for (int j = 0; j < NTj; j++)
#pragma unroll
            for (int k = 0; k < 4; k++) acc[i][j][k] = 0.f;

#pragma unroll
    for (int s = 0; s < STAGES - 1; s++) loadStage(s);

    for (int kt = 0; kt < KT; kt++) {
        asm volatile("cp.async.wait_group %0;" :: "n"(STAGES - 2));
        __syncthreads();    // stage kt data ready; also covers rMax/rInv on kt==0
        loadStage(kt + STAGES - 1);

        // transform A region of stage kt: prob = bit ? exp(x-max)*inv : 0
        char* sbase = smem + (kt & 3) * STGB;
#pragma unroll
        for (int i = 0; i < 4; i++) {
            int id = tid + i * 256;
            int r = id >> 3, c = id & 7;
            uint4* ptr = (uint4*)(sbase + r * 128 + ((c ^ (r & 7)) << 4));
            uint4 v = *ptr;
            u32 bb = Mrow[(long)r * (S_ / 32) + kt * 2 + (c >> 2)] >> ((c & 3) * 8);
            const float mx = rMax[r], inv = rInv[r];
            __half2* h2 = (__half2*)&v;
#pragma unroll
            for (int e = 0; e < 4; e++) {
                float2 f = __half22float2(h2[e]);
                f.x = ((bb >> (e * 2)) & 1)     ? expf(f.x - mx) * inv : 0.f;
                f.y = ((bb >> (e * 2 + 1)) & 1) ? expf(f.y - mx) * inv : 0.f;
                h2[e] = __floats2half2_rn(f.x, f.y);
            }
            *ptr = v;
        }
        __syncthreads();    // probs visible before ldmatrix

        const u32 sA = sb + (kt & 3) * STGB;
        const u32 sB = sA + BM * 128;
#pragma unroll
        for (int ks = 0; ks < 4; ks++) {
            u32 af[MT][4], bf[NTj][2];
            const int ca = ks * 2 + ksegA;
            const int cb = ks * 2 + ksegB;
#pragma unroll
            for (int i = 0; i < MT; i++)
                ldsm4(af[i][0], af[i][1], af[i][2], af[i][3],
                      sA + aRow[i] + ((ca ^ aSw[i]) << 4));
#pragma unroll
            for (int j = 0; j < NTj / 2; j++)
                ldsm4(bf[2 * j][0], bf[2 * j][1], bf[2 * j + 1][0], bf[2 * j + 1][1],
                      sB + bRow[j] + ((cb ^ bSw[j]) << 4));
#pragma unroll
            for (int i = 0; i < MT; i++)
#pragma unroll
                for (int j = 0; j < NTj; j++)
                    mma16(acc[i][j], af[i], bf[j]);
        }
    }

    // epilogue: Oh[b][q][h*64+d] fp16
    __half* C = Og + (long)b * S_ * D_ + h * DK_;
#pragma unroll
    for (int i = 0; i < MT; i++) {
        const long r0 = q0 + wm * 32 + i * 16 + g;
#pragma unroll
        for (int j = 0; j < NTj; j++) {
            const long c = wn * 32 + j * 8 + tg * 2;
            *(__half2*)(C + r0 * D_ + c) =
                __floats2half2_rn(acc[i][j][0], acc[i][j][1]);
            *(__half2*)(C + (r0 + 8) * D_ + c) =
                __floats2half2_rn(acc[i][j][2], acc[i][j][3]);
        }
    }
}

// ---------------- mask bitpack ----------------
__global__ __launch_bounds__(256) void pack_k(const int* __restrict__ mask,
                                              u32* __restrict__ out) {
    const long i = (long)blockIdx.x * 256 + threadIdx.x;
    const int  m = mask[i];
    const u32  w = __ballot_sync(0xffffffffu, m != 0);
    if ((threadIdx.x & 31) == 0) out[i >> 5] = w;
}

// ---------------- batched fp32 -> fp16 converts (4 tensors, z-indexed) -------
struct CV { const float4* in[4]; uint2* out[4]; };
__global__ __launch_bounds__(256) void cvt4_k(CV cp) {
    const int z = blockIdx.z;
    long i = (long)blockIdx.x * 256 + threadIdx.x;
    float4 v = cp.in[z][i];
    __half2 lo = __floats2half2_rn(v.x, v.y);
    __half2 hi = __floats2half2_rn(v.z, v.w);
    cp.out[z][i] = make_uint2(*(u32*)&lo, *(u32*)&hi);
}

// ---------------- batched weight transposes (4 weights, z-indexed) ----------
struct TR { const float* in[4]; __half* out[4]; };
__global__ __launch_bounds__(256) void tr4_k(TR tp) {
    __shared__ float t[32][33];
    const int z = blockIdx.z;
    const float* in = tp.in[z];
    __half* out = tp.out[z];
    const int bx = blockIdx.x * 32, by = blockIdx.y * 32;
    const int x = threadIdx.x & 31, y0 = (threadIdx.x >> 5) * 4;
#pragma unroll
    for (int i = 0; i < 4; i++)
        t[y0 + i][x] = in[(long)(by + y0 + i) * D_ + bx + x];
    __syncthreads();
#pragma unroll
    for (int i = 0; i < 4; i++)
        out[(long)(bx + y0 + i) * D_ + by + x] = __float2half_rn(t[x][y0 + i]);
}

// ---------------- softmax stats: per-row masked (max, 1/sum) -----------------
__global__ __launch_bounds__(256) void stats_k(const __half* __restrict__ S,
                                               const u32* __restrict__ maskb,
                                               float2* __restrict__ RS) {
    const long r  = blockIdx.x;                 // [0, B*H*S)
    const int  q  = (int)(r & (S_ - 1));
    const int  bh = (int)(r >> 11);
    const int  b  = bh >> 4;
    const __half* row = S + r * (long)S_;
    const u32* mrow = maskb + ((long)b * S_ + q) * (S_ / 32);
    const int tid = threadIdx.x;

    uint4 xr = ((const uint4*)row)[tid];        // 8 halves
    const u32 mw    = mrow[tid >> 2];
    const u32 mbits = (mw >> ((tid & 3) * 8)) & 0xFFu;
    const __half2* hp = (const __half2*)&xr;
    float xs[8];
#pragma unroll
    for (int i = 0; i < 4; i++) {
        float2 f = __half22float2(hp[i]);
        xs[i * 2] = f.x; xs[i * 2 + 1] = f.y;
    }

    float lmax = -3.402823466e38f;
#pragma unroll
    for (int i = 0; i < 8; i++)
        if ((mbits >> i) & 1) lmax = fmaxf(lmax, xs[i]);
#pragma unroll
    for (int o = 16; o > 0; o >>= 1)
        lmax = fmaxf(lmax, __shfl_xor_sync(0xffffffffu, lmax, o));

    __shared__ float sm[8];
    if ((tid & 31) == 0) sm[tid >> 5] = lmax;
    __syncthreads();
    float bmax = sm[0];
#pragma unroll
    for (int i = 1; i < 8; i++) bmax = fmaxf(bmax, sm[i]);
    __syncthreads();

    float lsum = 0.f;
#pragma unroll
    for (int i = 0; i < 8; i++)
        lsum += ((mbits >> i) & 1) ? expf(xs[i] - bmax) : 0.f;
#pragma unroll
    for (int o = 16; o > 0; o >>= 1)
        lsum += __shfl_xor_sync(0xffffffffu, lsum, o);
    if ((tid & 31) == 0) sm[tid >> 5] = lsum;
    __syncthreads();

    if (tid == 0) {
        float bsum = 0.f;
#pragma unroll
        for (int i = 0; i < 8; i++) bsum += sm[i];
        RS[r] = make_float2(bmax, (bsum > 0.f) ? 1.f / bsum : 0.f);
    }
}

// ---------------- launch ----------------
#define SMEM_BIG (4 * (128 + 256) * 128)   // 196608
#define SMEM_QK  (2 * (128 + 128) * 128)   //  65536
#define SMEM_AV  (4 * (128 + 64) * 128)    //  98304

extern "C" void kernel_launch(void* const* d_in, const int* in_sizes, int n_in,
                              void* d_out, int out_size) {
    (void)in_sizes; (void)n_in; (void)out_size;
    const float* inq  = (const float*)d_in[0];
    const float* ink  = (const float*)d_in[1];
    const float* invv = (const float*)d_in[2];
    const int*   mask = (const int*)d_in[3];
    const float* prop = (const float*)d_in[4];
    const float* Wq = (const float*)d_in[5];
    const float* bq = (const float*)d_in[6];
    const float* Wk = (const float*)d_in[7];
    const float* bk = (const float*)d_in[8];
    const float* Wv = (const float*)d_in[9];
    const float* bv = (const float*)d_in[10];
    const float* Wo = (const float*)d_in[11];
    const float* bo = (const float*)d_in[12];

    __half *Xq, *Xk, *Xv, *Qh, *Kh, *Vt, *Oh, *Ph, *Wqt, *Wkt, *Wvt, *Wot, *S1, *S2;
    u32* Mb;
    float2* RS;
    cudaGetSymbolAddress((void**)&Xq, g_Xq);
    cudaGetSymbolAddress((void**)&Xk, g_Xk);
    cudaGetSymbolAddress((void**)&Xv, g_Xv);
    cudaGetSymbolAddress((void**)&Qh, g_Qh);
    cudaGetSymbolAddress((void**)&Kh, g_Kh);
    cudaGetSymbolAddress((void**)&Vt, g_Vt);
    cudaGetSymbolAddress((void**)&Oh, g_Oh);
    cudaGetSymbolAddress((void**)&Ph, g_Ph);
    cudaGetSymbolAddress((void**)&Wqt, g_Wqt);
    cudaGetSymbolAddress((void**)&Wkt, g_Wkt);
    cudaGetSymbolAddress((void**)&Wvt, g_Wvt);
    cudaGetSymbolAddress((void**)&Wot, g_Wot);
    cudaGetSymbolAddress((void**)&S1, g_S1);
    cudaGetSymbolAddress((void**)&S2, g_S2);
    cudaGetSymbolAddress((void**)&Mb, g_Mb);
    cudaGetSymbolAddress((void**)&RS, g_RS);

    cudaFuncSetAttribute((gemm_l<128, 256, 2, 4, 5, 4>),    cudaFuncAttributeMaxDynamicSharedMemorySize, SMEM_BIG);
    cudaFuncSetAttribute((gemm_l<128, 128, 2, 4, 2, 2, 2>), cudaFuncAttributeMaxDynamicSharedMemorySize, SMEM_QK);
    cudaFuncSetAttribute((gemm_l<128, 256, 2, 4, 0, 4>),    cudaFuncAttributeMaxDynamicSharedMemorySize, SMEM_BIG);
    cudaFuncSetAttribute((gemm_l<128, 256, 2, 4, 4, 4>),    cudaFuncAttributeMaxDynamicSharedMemorySize, SMEM_BIG);
    cudaFuncSetAttribute(av_fused, cudaFuncAttributeMaxDynamicSharedMemorySize, SMEM_AV);

    dim3 blk(256);

    // 0: conversions (z-batched) + bitpack + weight transposes (z-batched)
    {
        CV cp;
        cp.in[0] = (const float4*)inq;  cp.out[0] = (uint2*)Xq;
        cp.in[1] = (const float4*)ink;  cp.out[1] = (uint2*)Xk;
        cp.in[2] = (const float4*)invv; cp.out[2] = (uint2*)Xv;
        cp.in[3] = (const float4*)prop; cp.out[3] = (uint2*)Ph;
        cvt4_k<<<dim3(4096, 1, 4), blk>>>(cp);
        pack_k<<<(int)(((long)B_ * S_ * S_) / 256), blk>>>(mask, Mb);
        TR tp;
        tp.in[0] = Wq; tp.out[0] = Wqt;
        tp.in[1] = Wk; tp.out[1] = Wkt;
        tp.in[2] = Wv; tp.out[2] = Wvt;
        tp.in[3] = Wo; tp.out[3] = Wot;
        tr4_k<<<dim3(D_ / 32, D_ / 32, 4), blk>>>(tp);
    }

    // 1: all three projections in one launch (z = 0:Q, 1:K, 2:V-transposed)
    {
        HP p{};
        p.lda = D_; p.ldb = D_; p.ldc = D_;
        p.K = D_;
        p.A  = Xq; p.Bm  = Wqt; p.C  = Qh; p.bias  = bq;
        p.A1 = Xk; p.Bm1 = Wkt; p.C1 = Kh; p.bias1 = bk;
        p.A2 = Xv; p.Bm2 = Wvt; p.C2 = Vt; p.bias2 = bv;
        dim3 grid(D_ / 256, (B_ * S_) / 128, 3);
        gemm_l<128, 256, 2, 4, 5, 4><<<grid, blk, SMEM_BIG>>>(p);
    }

    // 2: S1 = maskbit ? (Q.K^T)/8 : 0   (batched NT, K=64; 128x128, 2 CTAs/SM)
    {
        HP p{};
        p.A = Qh; p.lda = D_; p.Ab = (long)S_ * D_; p.Ah = DK_;
        p.Bm = Kh; p.ldb = D_; p.Bb = (long)S_ * D_; p.Bh = DK_;
        p.C = S1; p.ldc = S_; p.Cb = (long)H_ * S_ * S_; p.Ch = (long)S_ * S_;
        p.mask = Mb; p.maskB = (long)S_ * S_ / 32;
        p.scale = 0.125f;
        p.K = DK_;
        dim3 grid(S_ / 128, S_ / 128, B_ * H_);
        gemm_l<128, 128, 2, 4, 2, 2, 2><<<grid, blk, SMEM_QK>>>(p);
    }

    // 3: S2 = S1 @ P^T   (batched NT, K=2048 — tensor-roofline GEMM)
    {
        HP p{};
        p.A = S1; p.lda = S_; p.Ab = (long)H_ * S_ * S_; p.Ah = (long)S_ * S_;
        p.Bm = Ph; p.ldb = S_;
        p.C = S2; p.ldc = S_; p.Cb = (long)H_ * S_ * S_; p.Ch = (long)S_ * S_;
        p.K = S_;
        dim3 grid(S_ / 256, S_ / 128, B_ * H_);
        gemm_l<128, 256, 2, 4, 0, 4><<<grid, blk, SMEM_BIG>>>(p);
    }

    // 4: softmax stats only (max, 1/sum per row) — no 256 MB rewrite
    stats_k<<<B_ * H_ * S_, blk>>>(S2, Mb, RS);

    // 5: Oh = softmax(S2) @ V, probs computed on the fly in smem
    {
        dim3 grid(1, S_ / 128, B_ * H_);
        av_fused<<<grid, blk, SMEM_AV>>>(S2, Vt, Oh, Mb, RS);
    }

    // 6: out = Oh @ Wo + bo   (NT, fp32 store)
    {
        HP p{};
        p.A = Oh; p.lda = D_;
        p.Bm = Wot; p.ldb = D_;
        p.bias = bo;
        p.C = d_out; p.ldc = D_;
        p.K = D_;
        dim3 grid(D_ / 256, (B_ * S_) / 128, 1);
        gemm_l<128, 256, 2, 4, 4, 4><<<grid, blk, SMEM_BIG>>>(p);
    }
}

// round 15
// speedup vs baseline: 1.0613x; 1.0613x over previous
#include <cuda_runtime.h>
#include <cuda_fp16.h>
#include <cstdint>

#define B_  2
#define S_  2048
#define D_  1024
#define H_  16
#define DK_ 64

typedef unsigned int u32;

// ---------------- scratch (device globals: allocation-free) ----------------
__device__ __half g_Xq[(size_t)B_ * S_ * D_];
__device__ __half g_Xk[(size_t)B_ * S_ * D_];
__device__ __half g_Xv[(size_t)B_ * S_ * D_];
__device__ __half g_Qh[(size_t)B_ * S_ * D_];
__device__ __half g_Kh[(size_t)B_ * S_ * D_];
__device__ __half g_Vt[(size_t)B_ * S_ * D_];      // V transposed [b][h][dk][S]
__device__ __half g_Oh[(size_t)B_ * S_ * D_];
__device__ __half g_Ph[(size_t)S_ * S_];
__device__ __half g_Wqt[(size_t)D_ * D_];
__device__ __half g_Wkt[(size_t)D_ * D_];
__device__ __half g_Wvt[(size_t)D_ * D_];
__device__ __half g_Wot[(size_t)D_ * D_];
__device__ __half g_S1[(size_t)B_ * H_ * S_ * S_]; // 256 MB
__device__ __half g_S2[(size_t)B_ * H_ * S_ * S_]; // 256 MB
__device__ u32    g_Mb[(size_t)B_ * S_ * S_ / 32]; // bitpacked mask (1 MB)

// ---------------- asm helpers ----------------
__device__ __forceinline__ void mma16(float* c, const u32* a, const u32* b) {
    asm volatile(
        "mma.sync.aligned.m16n8k16.row.col.f32.f16.f16.f32 "
        "{%0,%1,%2,%3},{%4,%5,%6,%7},{%8,%9},{%0,%1,%2,%3};\n"
        : "+f"(c[0]), "+f"(c[1]), "+f"(c[2]), "+f"(c[3])
        : "r"(a[0]), "r"(a[1]), "r"(a[2]), "r"(a[3]), "r"(b[0]), "r"(b[1]));
}

__device__ __forceinline__ void ldsm4(u32& r0, u32& r1, u32& r2, u32& r3, u32 a) {
    asm volatile("ldmatrix.sync.aligned.m8n8.x4.shared.b16 {%0,%1,%2,%3}, [%4];"
                 : "=r"(r0), "=r"(r1), "=r"(r2), "=r"(r3) : "r"(a));
}

__device__ __forceinline__ u32 smem_u32(const void* p) {
    u32 a;
    asm("{ .reg .u64 t; cvta.to.shared.u64 t, %1; cvt.u32.u64 %0, t; }"
        : "=r"(a) : "l"(p));
    return a;
}

__device__ __forceinline__ void cpa16(u32 dst, const void* src) {
    asm volatile("cp.async.cg.shared.global [%0], [%1], 16;" :: "r"(dst), "l"(src));
}
#define CP_COMMIT() asm volatile("cp.async.commit_group;" ::: "memory")

struct HP {
    const __half* A;
    const __half* Bm;
    void*         C;
    const float*  bias;
    const u32*    mask;       // bitpacked
    const __half *A1, *A2, *Bm1, *Bm2;   // EPI5 (triple projection)
    void *C1, *C2;
    const float *bias1, *bias2;
    long lda, ldb, ldc;
    long Ab, Ah, Bb, Bh, Cb, Ch, maskB;
    float scale;
    int  K;
};

// ---------------- fp16 NT GEMM template ----------------
// EPI: 0 plain fp16, 2 maskbit?v*scale:0 fp16, 4 +bias fp32,
//      5 triple-projection (z selects operands; z==2 stores transposed V)
template<int BM, int BN, int WMN, int WNN, int EPI, int STAGES, int MINB = 1>
__global__ __launch_bounds__(256, MINB) void gemm_l(HP p) {
    static_assert(WMN * WNN == 8, "8 warps");
    constexpr int WTM  = BM / WMN;
    constexpr int WTN  = BN / WNN;
    constexpr int MT   = WTM / 16;
    constexpr int NTj  = WTN / 8;
    constexpr int STGB = (BM + BN) * 128;
    constexpr int CHK  = (BM + BN) * 8 / 256;

    extern __shared__ __align__(1024) char smem[];
    const u32 sb = smem_u32(smem);

    const int tid  = threadIdx.x;
    const int wid  = tid >> 5, lane = tid & 31;
    const int wm   = wid / WNN, wn = wid % WNN;
    const int g    = lane >> 2, tg = lane & 3;
    const int z    = blockIdx.z;
    const int b    = z / H_, h = z % H_;

    const __half *Abase, *Bbase;
    if constexpr (EPI == 5) {
        Abase = (z == 0) ? p.A : (z == 1) ? p.A1 : p.A2;
        Bbase = (z == 0) ? p.Bm : (z == 1) ? p.Bm1 : p.Bm2;
    } else {
        Abase = p.A + (long)b * p.Ab + (long)h * p.Ah;
        Bbase = p.Bm + (long)b * p.Bb + (long)h * p.Bh;
    }
    const __half* Ab = Abase + (long)blockIdx.y * BM * p.lda;
    const __half* Bb = Bbase + (long)blockIdx.x * BN * p.ldb;

    const int KT = p.K >> 6;

    int cR[CHK], cC[CHK];
#pragma unroll
    for (int i = 0; i < CHK; i++) {
        int id = tid + i * 256;
        cR[i] = id >> 3;
        cC[i] = id & 7;
    }

    auto loadStage = [&](int kt) {
        if (kt < KT) {
            const u32 s0 = sb + (kt % STAGES) * STGB;
#pragma unroll
            for (int i = 0; i < CHK; i++) {
                int r = cR[i], c = cC[i];
                if (r < BM) {
                    cpa16(s0 + r * 128 + ((c ^ (r & 7)) << 4),
                          Ab + (long)r * p.lda + kt * 64 + c * 8);
                } else {
                    int rr = r - BM;
                    cpa16(s0 + BM * 128 + rr * 128 + ((c ^ (rr & 7)) << 4),
                          Bb + (long)rr * p.ldb + kt * 64 + c * 8);
                }
            }
        }
        CP_COMMIT();
    };

    const int la = lane & 7;
    const int ksegA = (lane >> 4) & 1;
    const int ksegB = (lane >> 3) & 1;
    int aRow[MT], aSw[MT], bRow[NTj / 2], bSw[NTj / 2];
#pragma unroll
    for (int i = 0; i < MT; i++) {
        int r = wm * WTM + i * 16 + ((lane >> 3) & 1) * 8 + la;
        aRow[i] = r * 128;
        aSw[i]  = r & 7;
    }
#pragma unroll
    for (int j = 0; j < NTj / 2; j++) {
        int r = wn * WTN + j * 16 + ((lane >> 4) & 1) * 8 + la;
        bRow[j] = r * 128;
        bSw[j]  = r & 7;
    }

    float acc[MT][NTj][4];
#pragma unroll
    for (int i = 0; i < MT; i++)
#pragma unroll
        for (int j = 0; j < NTj; j++)
#pragma unroll
            for (int k = 0; k < 4; k++) acc[i][j][k] = 0.f;

#pragma unroll
    for (int s = 0; s < STAGES - 1; s++) loadStage(s);

    for (int kt = 0; kt < KT; kt++) {
        asm volatile("cp.async.wait_group %0;" :: "n"(STAGES - 2));
        __syncthreads();
        loadStage(kt + STAGES - 1);

        const u32 sA = sb + (kt % STAGES) * STGB;
        const u32 sB = sA + BM * 128;
#pragma unroll
        for (int ks = 0; ks < 4; ks++) {
            u32 af[MT][4], bf[NTj][2];
            const int ca = ks * 2 + ksegA;
            const int cb = ks * 2 + ksegB;
#pragma unroll
            for (int i = 0; i < MT; i++)
                ldsm4(af[i][0], af[i][1], af[i][2], af[i][3],
                      sA + aRow[i] + ((ca ^ aSw[i]) << 4));
#pragma unroll
            for (int j = 0; j < NTj / 2; j++)
                ldsm4(bf[2 * j][0], bf[2 * j][1], bf[2 * j + 1][0], bf[2 * j + 1][1],
                      sB + bRow[j] + ((cb ^ bSw[j]) << 4));
#pragma unroll
            for (int i = 0; i < MT; i++)
#pragma unroll
                for (int j = 0; j < NTj; j++)
                    mma16(acc[i][j], af[i], bf[j]);
        }
    }

    // ---------------- epilogue ----------------
    const long row0 = (long)blockIdx.y * BM + wm * WTM;
    const long col0 = (long)blockIdx.x * BN + wn * WTN;

#pragma unroll
    for (int i = 0; i < MT; i++) {
        const long r0 = row0 + i * 16 + g;
#pragma unroll
        for (int j = 0; j < NTj; j++) {
            const long c = col0 + j * 8 + tg * 2;
            float v0 = acc[i][j][0], v1 = acc[i][j][1];
            float v2 = acc[i][j][2], v3 = acc[i][j][3];
            if constexpr (EPI == 4) {
                float b0 = p.bias[c], b1 = p.bias[c + 1];
                v0 += b0; v1 += b1; v2 += b0; v3 += b1;
                float* C = (float*)p.C + (long)b * p.Cb + (long)h * p.Ch;
                *(float2*)(C + r0 * p.ldc + c)       = make_float2(v0, v1);
                *(float2*)(C + (r0 + 8) * p.ldc + c) = make_float2(v2, v3);
            } else if constexpr (EPI == 2) {
                const u32* mb = p.mask + (long)b * p.maskB;
                const int  wofs = (int)(c >> 5), sh = (int)(c & 31);
                u32 w0 = mb[r0 * (S_ / 32) + wofs];
                u32 w1 = mb[(r0 + 8) * (S_ / 32) + wofs];
                v0 = (w0 >> sh) & 1       ? v0 * p.scale : 0.f;
                v1 = (w0 >> (sh + 1)) & 1 ? v1 * p.scale : 0.f;
                v2 = (w1 >> sh) & 1       ? v2 * p.scale : 0.f;
                v3 = (w1 >> (sh + 1)) & 1 ? v3 * p.scale : 0.f;
                __half* C = (__half*)p.C + (long)b * p.Cb + (long)h * p.Ch;
                *(__half2*)(C + r0 * p.ldc + c)       = __floats2half2_rn(v0, v1);
                *(__half2*)(C + (r0 + 8) * p.ldc + c) = __floats2half2_rn(v2, v3);
            } else if constexpr (EPI == 5) {
                const float* bs = (z == 0) ? p.bias : (z == 1) ? p.bias1 : p.bias2;
                float b0 = bs[c], b1 = bs[c + 1];
                v0 += b0; v1 += b1; v2 += b0; v3 += b1;
                if (z == 2) {
                    __half* Ct = (__half*)p.C2;
                    const int hh = (int)(c >> 6), d = (int)(c & 63);
                    {
                        const long bb = r0 >> 11, s = r0 & (S_ - 1);
                        __half* base = Ct + ((bb * H_ + hh) * 64 + d) * (long)S_ + s;
                        base[0]  = __float2half_rn(v0);
                        base[S_] = __float2half_rn(v1);
                    }
                    {
                        const long bb = (r0 + 8) >> 11, s = (r0 + 8) & (S_ - 1);
                        __half* base = Ct + ((bb * H_ + hh) * 64 + d) * (long)S_ + s;
                        base[0]  = __float2half_rn(v2);
                        base[S_] = __float2half_rn(v3);
                    }
                } else {
                    __half* C = (__half*)(z == 0 ? p.C : p.C1);
                    *(__half2*)(C + r0 * p.ldc + c)       = __floats2half2_rn(v0, v1);
                    *(__half2*)(C + (r0 + 8) * p.ldc + c) = __floats2half2_rn(v2, v3);
                }
            } else {
                __half* C = (__half*)p.C + (long)b * p.Cb + (long)h * p.Ch;
                *(__half2*)(C + r0 * p.ldc + c)       = __floats2half2_rn(v0, v1);
                *(__half2*)(C + (r0 + 8) * p.ldc + c) = __floats2half2_rn(v2, v3);
            }
        }
    }
}

// ---------------- mask bitpack ----------------
__global__ __launch_bounds__(256) void pack_k(const int* __restrict__ mask,
                                              u32* __restrict__ out) {
    const long i = (long)blockIdx.x * 256 + threadIdx.x;
    const int  m = mask[i];
    const u32  w = __ballot_sync(0xffffffffu, m != 0);
    if ((threadIdx.x & 31) == 0) out[i >> 5] = w;
}

// ---------------- batched fp32 -> fp16 converts (3 inputs, z-indexed) --------
struct CV { const float4* in[4]; uint2* out[4]; };
__global__ __launch_bounds__(256) void cvt3_k(CV cp) {
    const int z = blockIdx.z;
    long i = (long)blockIdx.x * 256 + threadIdx.x;
    float4 v = cp.in[z][i];
    __half2 lo = __floats2half2_rn(v.x, v.y);
    __half2 hi = __floats2half2_rn(v.z, v.w);
    cp.out[z][i] = make_uint2(*(u32*)&lo, *(u32*)&hi);
}

// ---------------- single fp32 -> fp16 convert (P matrix) ----------
__global__ __launch_bounds__(256) void cvt1_k(const float4* __restrict__ in,
                                              uint2* __restrict__ out) {
    long i = (long)blockIdx.x * 256 + threadIdx.x;
    float4 v = in[i];
    __half2 lo = __floats2half2_rn(v.x, v.y);
    __half2 hi = __floats2half2_rn(v.z, v.w);
    out[i] = make_uint2(*(u32*)&lo, *(u32*)&hi);
}

// ---------------- batched weight transposes (4 weights, z-indexed) ----------
struct TR { const float* in[4]; __half* out[4]; };
__global__ __launch_bounds__(256) void tr4_k(TR tp) {
    __shared__ float t[32][33];
    const int z = blockIdx.z;
    const float* in = tp.in[z];
    __half* out = tp.out[z];
    const int bx = blockIdx.x * 32, by = blockIdx.y * 32;
    const int x = threadIdx.x & 31, y0 = (threadIdx.x >> 5) * 4;
#pragma unroll
    for (int i = 0; i < 4; i++)
        t[y0 + i][x] = in[(long)(by + y0 + i) * D_ + bx + x];
    __syncthreads();
#pragma unroll
    for (int i = 0; i < 4; i++)
        out[(long)(bx + y0 + i) * D_ + by + x] = __float2half_rn(t[x][y0 + i]);
}

// ---------------- masked softmax + nan_to_num, fp16 in-place, bit mask -------
__global__ __launch_bounds__(256) void softmax_h(__half* __restrict__ S,
                                                 const u32* __restrict__ maskb) {
    const long r  = blockIdx.x;                 // [0, B*H*S)
    const int  q  = (int)(r & (S_ - 1));
    const int  bh = (int)(r >> 11);
    const int  b  = bh >> 4;
    __half* row = S + r * (long)S_;
    const u32* mrow = maskb + ((long)b * S_ + q) * (S_ / 32);
    const int tid = threadIdx.x;

    uint4 xr = ((const uint4*)row)[tid];        // 8 halves
    const u32 mw    = mrow[tid >> 2];
    const u32 mbits = (mw >> ((tid & 3) * 8)) & 0xFFu;
    const __half2* hp = (const __half2*)&xr;
    float xs[8];
#pragma unroll
    for (int i = 0; i < 4; i++) {
        float2 f = __half22float2(hp[i]);
        xs[i * 2] = f.x; xs[i * 2 + 1] = f.y;
    }

    float lmax = -3.402823466e38f;
#pragma unroll
    for (int i = 0; i < 8; i++)
        if ((mbits >> i) & 1) lmax = fmaxf(lmax, xs[i]);
#pragma unroll
    for (int o = 16; o > 0; o >>= 1)
        lmax = fmaxf(lmax, __shfl_xor_sync(0xffffffffu, lmax, o));

    __shared__ float sm[8];
    if ((tid & 31) == 0) sm[tid >> 5] = lmax;
    __syncthreads();
    float bmax = sm[0];
#pragma unroll
    for (int i = 1; i < 8; i++) bmax = fmaxf(bmax, sm[i]);
    __syncthreads();

    float es[8];
    float lsum = 0.f;
#pragma unroll
    for (int i = 0; i < 8; i++) {
        es[i] = ((mbits >> i) & 1) ? expf(xs[i] - bmax) : 0.f;
        lsum += es[i];
    }
#pragma unroll
    for (int o = 16; o > 0; o >>= 1)
        lsum += __shfl_xor_sync(0xffffffffu, lsum, o);
    if ((tid & 31) == 0) sm[tid >> 5] = lsum;
    __syncthreads();
    float bsum = 0.f;
#pragma unroll
    for (int i = 0; i < 8; i++) bsum += sm[i];

    const float inv = (bsum > 0.f) ? 1.f / bsum : 0.f;
    uint4 outr;
    __half2* op = (__half2*)&outr;
#pragma unroll
    for (int i = 0; i < 4; i++)
        op[i] = __floats2half2_rn(es[i * 2] * inv, es[i * 2 + 1] * inv);
    ((uint4*)row)[tid] = outr;
}

// ---------------- launch ----------------
#define SMEM_BIG (4 * (128 + 256) * 128)   // 196608
#define SMEM_QK  (2 * (128 + 128) * 128)   //  65536
#define SMEM_AV  (4 * (128 + 64) * 128)    //  98304

extern "C" void kernel_launch(void* const* d_in, const int* in_sizes, int n_in,
                              void* d_out, int out_size) {
    (void)in_sizes; (void)n_in; (void)out_size;
    const float* inq  = (const float*)d_in[0];
    const float* ink  = (const float*)d_in[1];
    const float* invv = (const float*)d_in[2];
    const int*   mask = (const int*)d_in[3];
    const float* prop = (const float*)d_in[4];
    const float* Wq = (const float*)d_in[5];
    const float* bq = (const float*)d_in[6];
    const float* Wk = (const float*)d_in[7];
    const float* bk = (const float*)d_in[8];
    const float* Wv = (const float*)d_in[9];
    const float* bv = (const float*)d_in[10];
    const float* Wo = (const float*)d_in[11];
    const float* bo = (const float*)d_in[12];

    __half *Xq, *Xk, *Xv, *Qh, *Kh, *Vt, *Oh, *Ph, *Wqt, *Wkt, *Wvt, *Wot, *S1, *S2;
    u32* Mb;
    cudaGetSymbolAddress((void**)&Xq, g_Xq);
    cudaGetSymbolAddress((void**)&Xk, g_Xk);
    cudaGetSymbolAddress((void**)&Xv, g_Xv);
    cudaGetSymbolAddress((void**)&Qh, g_Qh);
    cudaGetSymbolAddress((void**)&Kh, g_Kh);
    cudaGetSymbolAddress((void**)&Vt, g_Vt);
    cudaGetSymbolAddress((void**)&Oh, g_Oh);
    cudaGetSymbolAddress((void**)&Ph, g_Ph);
    cudaGetSymbolAddress((void**)&Wqt, g_Wqt);
    cudaGetSymbolAddress((void**)&Wkt, g_Wkt);
    cudaGetSymbolAddress((void**)&Wvt, g_Wvt);
    cudaGetSymbolAddress((void**)&Wot, g_Wot);
    cudaGetSymbolAddress((void**)&S1, g_S1);
    cudaGetSymbolAddress((void**)&S2, g_S2);
    cudaGetSymbolAddress((void**)&Mb, g_Mb);

    cudaFuncSetAttribute((gemm_l<128, 256, 2, 4, 5, 4>),    cudaFuncAttributeMaxDynamicSharedMemorySize, SMEM_BIG);
    cudaFuncSetAttribute((gemm_l<128, 128, 2, 4, 2, 2, 2>), cudaFuncAttributeMaxDynamicSharedMemorySize, SMEM_QK);
    cudaFuncSetAttribute((gemm_l<128, 256, 2, 4, 0, 4>),    cudaFuncAttributeMaxDynamicSharedMemorySize, SMEM_BIG);
    cudaFuncSetAttribute((gemm_l<128, 256, 2, 4, 4, 4>),    cudaFuncAttributeMaxDynamicSharedMemorySize, SMEM_BIG);
    cudaFuncSetAttribute((gemm_l<128, 64, 4, 2, 0, 4, 2>),  cudaFuncAttributeMaxDynamicSharedMemorySize, SMEM_AV);

    // side stream + events (capture-safe fork/join, verified in R13)
    cudaStream_t sB;
    cudaStreamCreateWithFlags(&sB, cudaStreamNonBlocking);
    cudaEvent_t eFork, ePrep;
    cudaEventCreateWithFlags(&eFork, cudaEventDisableTiming);
    cudaEventCreateWithFlags(&ePrep, cudaEventDisableTiming);

    dim3 blk(256);

    // fork point: sB starts at capture origin
    cudaEventRecord(eFork, 0);
    cudaStreamWaitEvent(sB, eFork, 0);

    // ---- sB: mask bitpack + P convert (not needed until QK^T / prop) ----
    pack_k<<<(int)(((long)B_ * S_ * S_) / 256), blk, 0, sB>>>(mask, Mb);
    cvt1_k<<<(int)(((long)S_ * S_) / 1024), blk, 0, sB>>>((const float4*)prop, (uint2*)Ph);
    cudaEventRecord(ePrep, sB);

    // ---- s0: input converts + weight transposes (needed by projections) ----
    {
        CV cp;
        cp.in[0] = (const float4*)inq;  cp.out[0] = (uint2*)Xq;
        cp.in[1] = (const float4*)ink;  cp.out[1] = (uint2*)Xk;
        cp.in[2] = (const float4*)invv; cp.out[2] = (uint2*)Xv;
        cp.in[3] = (const float4*)inq;  cp.out[3] = (uint2*)Xq;   // unused z<3
        cvt3_k<<<dim3(4096, 1, 3), blk>>>(cp);
        TR tp;
        tp.in[0] = Wq; tp.out[0] = Wqt;
        tp.in[1] = Wk; tp.out[1] = Wkt;
        tp.in[2] = Wv; tp.out[2] = Wvt;
        tp.in[3] = Wo; tp.out[3] = Wot;
        tr4_k<<<dim3(D_ / 32, D_ / 32, 4), blk>>>(tp);
    }

    // 1: all three projections in one launch (z = 0:Q, 1:K, 2:V-transposed)
    {
        HP p{};
        p.lda = D_; p.ldb = D_; p.ldc = D_;
        p.K = D_;
        p.A  = Xq; p.Bm  = Wqt; p.C  = Qh; p.bias  = bq;
        p.A1 = Xk; p.Bm1 = Wkt; p.C1 = Kh; p.bias1 = bk;
        p.A2 = Xv; p.Bm2 = Wvt; p.C2 = Vt; p.bias2 = bv;
        dim3 grid(D_ / 256, (B_ * S_) / 128, 3);
        gemm_l<128, 256, 2, 4, 5, 4><<<grid, blk, SMEM_BIG>>>(p);
    }

    // join: mask bits + Ph ready before QK^T / prop
    cudaStreamWaitEvent(0, ePrep, 0);

    // 2: S1 = maskbit ? (Q.K^T)/8 : 0   (batched NT, K=64; 128x128, 2 CTAs/SM)
    {
        HP p{};
        p.A = Qh; p.lda = D_; p.Ab = (long)S_ * D_; p.Ah = DK_;
        p.Bm = Kh; p.ldb = D_; p.Bb = (long)S_ * D_; p.Bh = DK_;
        p.C = S1; p.ldc = S_; p.Cb = (long)H_ * S_ * S_; p.Ch = (long)S_ * S_;
        p.mask = Mb; p.maskB = (long)S_ * S_ / 32;
        p.scale = 0.125f;
        p.K = DK_;
        dim3 grid(S_ / 128, S_ / 128, B_ * H_);
        gemm_l<128, 128, 2, 4, 2, 2, 2><<<grid, blk, SMEM_QK>>>(p);
    }

    // 3: S2 = S1 @ P^T   (batched NT, K=2048 — tensor-roofline GEMM)
    {
        HP p{};
        p.A = S1; p.lda = S_; p.Ab = (long)H_ * S_ * S_; p.Ah = (long)S_ * S_;
        p.Bm = Ph; p.ldb = S_;
        p.C = S2; p.ldc = S_; p.Cb = (long)H_ * S_ * S_; p.Ch = (long)S_ * S_;
        p.K = S_;
        dim3 grid(S_ / 256, S_ / 128, B_ * H_);
        gemm_l<128, 256, 2, 4, 0, 4><<<grid, blk, SMEM_BIG>>>(p);
    }

    // 4: masked softmax + nan_to_num (in place, fp16, bit mask)
    softmax_h<<<B_ * H_ * S_, blk>>>(S2, Mb);

    // 5: Oh = probs @ V   (batched NT vs Vt, N=64, K=2048; 2 CTAs/SM)
    {
        HP p{};
        p.A = S2; p.lda = S_; p.Ab = (long)H_ * S_ * S_; p.Ah = (long)S_ * S_;
        p.Bm = Vt; p.ldb = S_; p.Bb = (long)H_ * DK_ * S_; p.Bh = (long)DK_ * S_;
        p.C = Oh; p.ldc = D_; p.Cb = (long)S_ * D_; p.Ch = DK_;
        p.K = S_;
        dim3 grid(1, S_ / 128, B_ * H_);
        gemm_l<128, 64, 4, 2, 0, 4, 2><<<grid, blk, SMEM_AV>>>(p);
    }

    // 6: out = Oh @ Wo + bo   (NT, fp32 store)
    {
        HP p{};
        p.A = Oh; p.lda = D_;
        p.Bm = Wot; p.ldb = D_;
        p.bias = bo;
        p.C = d_out; p.ldc = D_;
        p.K = D_;
        dim3 grid(D_ / 256, (B_ * S_) / 128, 1);
        gemm_l<128, 256, 2, 4, 4, 4><<<grid, blk, SMEM_BIG>>>(p);
    }
}

// round 16
// speedup vs baseline: 1.0723x; 1.0104x over previous
#include <cuda_runtime.h>
#include <cuda_fp16.h>
#include <cstdint>

#define B_  2
#define S_  2048
#define D_  1024
#define H_  16
#define DK_ 64

typedef unsigned int u32;

// ---------------- scratch (device globals: allocation-free) ----------------
__device__ __half g_Xq[(size_t)B_ * S_ * D_];
__device__ __half g_Xk[(size_t)B_ * S_ * D_];
__device__ __half g_Xv[(size_t)B_ * S_ * D_];
__device__ __half g_Qh[(size_t)B_ * S_ * D_];
__device__ __half g_Kh[(size_t)B_ * S_ * D_];
__device__ __half g_Vt[(size_t)B_ * S_ * D_];      // V transposed [b][h][dk][S]
__device__ __half g_Oh[(size_t)B_ * S_ * D_];
__device__ __half g_Ph[(size_t)S_ * S_];
__device__ __half g_Wqt[(size_t)D_ * D_];
__device__ __half g_Wkt[(size_t)D_ * D_];
__device__ __half g_Wvt[(size_t)D_ * D_];
__device__ __half g_Wot[(size_t)D_ * D_];
__device__ __half g_S1[(size_t)B_ * H_ * S_ * S_]; // 256 MB
__device__ __half g_S2[(size_t)B_ * H_ * S_ * S_]; // 256 MB
__device__ u32    g_Mb[(size_t)B_ * S_ * S_ / 32]; // bitpacked mask (1 MB)

// ---------------- asm helpers ----------------
__device__ __forceinline__ void mma16(float* c, const u32* a, const u32* b) {
    asm volatile(
        "mma.sync.aligned.m16n8k16.row.col.f32.f16.f16.f32 "
        "{%0,%1,%2,%3},{%4,%5,%6,%7},{%8,%9},{%0,%1,%2,%3};\n"
        : "+f"(c[0]), "+f"(c[1]), "+f"(c[2]), "+f"(c[3])
        : "r"(a[0]), "r"(a[1]), "r"(a[2]), "r"(a[3]), "r"(b[0]), "r"(b[1]));
}

__device__ __forceinline__ void ldsm4(u32& r0, u32& r1, u32& r2, u32& r3, u32 a) {
    asm volatile("ldmatrix.sync.aligned.m8n8.x4.shared.b16 {%0,%1,%2,%3}, [%4];"
                 : "=r"(r0), "=r"(r1), "=r"(r2), "=r"(r3) : "r"(a));
}

__device__ __forceinline__ u32 smem_u32(const void* p) {
    u32 a;
    asm("{ .reg .u64 t; cvta.to.shared.u64 t, %1; cvt.u32.u64 %0, t; }"
        : "=r"(a) : "l"(p));
    return a;
}

__device__ __forceinline__ void cpa16(u32 dst, const void* src) {
    asm volatile("cp.async.cg.shared.global [%0], [%1], 16;" :: "r"(dst), "l"(src));
}
#define CP_COMMIT() asm volatile("cp.async.commit_group;" ::: "memory")

struct HP {
    const __half* A;
    const __half* Bm;
    void*         C;
    const float*  bias;
    const u32*    mask;       // bitpacked
    const __half *A1, *A2, *Bm1, *Bm2;   // EPI5 (triple projection)
    void *C1, *C2;
    const float *bias1, *bias2;
    long lda, ldb, ldc;
    long Ab, Ah, Bb, Bh, Cb, Ch, maskB;
    float scale;
    int  K;
};

// ---------------- fp16 NT GEMM template ----------------
// EPI: 0 plain fp16, 2 maskbit?v*scale:0 fp16, 4 +bias fp32,
//      5 triple-projection (z selects operands; z==2 stores transposed V)
template<int BM, int BN, int WMN, int WNN, int EPI, int STAGES, int MINB = 1>
__global__ __launch_bounds__(256, MINB) void gemm_l(HP p) {
    static_assert(WMN * WNN == 8, "8 warps");
    constexpr int WTM  = BM / WMN;
    constexpr int WTN  = BN / WNN;
    constexpr int MT   = WTM / 16;
    constexpr int NTj  = WTN / 8;
    constexpr int STGB = (BM + BN) * 128;
    constexpr int CHK  = (BM + BN) * 8 / 256;

    extern __shared__ __align__(1024) char smem[];
    const u32 sb = smem_u32(smem);

    const int tid  = threadIdx.x;
    const int wid  = tid >> 5, lane = tid & 31;
    const int wm   = wid / WNN, wn = wid % WNN;
    const int g    = lane >> 2, tg = lane & 3;
    const int z    = blockIdx.z;
    const int b    = z / H_, h = z % H_;

    const __half *Abase, *Bbase;
    if constexpr (EPI == 5) {
        Abase = (z == 0) ? p.A : (z == 1) ? p.A1 : p.A2;
        Bbase = (z == 0) ? p.Bm : (z == 1) ? p.Bm1 : p.Bm2;
    } else {
        Abase = p.A + (long)b * p.Ab + (long)h * p.Ah;
        Bbase = p.Bm + (long)b * p.Bb + (long)h * p.Bh;
    }
    const __half* Ab = Abase + (long)blockIdx.y * BM * p.lda;
    const __half* Bb = Bbase + (long)blockIdx.x * BN * p.ldb;

    const int KT = p.K >> 6;

    int cR[CHK], cC[CHK];
#pragma unroll
    for (int i = 0; i < CHK; i++) {
        int id = tid + i * 256;
        cR[i] = id >> 3;
        cC[i] = id & 7;
    }

    auto loadStage = [&](int kt) {
        if (kt < KT) {
            const u32 s0 = sb + (kt % STAGES) * STGB;
#pragma unroll
            for (int i = 0; i < CHK; i++) {
                int r = cR[i], c = cC[i];
                if (r < BM) {
                    cpa16(s0 + r * 128 + ((c ^ (r & 7)) << 4),
                          Ab + (long)r * p.lda + kt * 64 + c * 8);
                } else {
                    int rr = r - BM;
                    cpa16(s0 + BM * 128 + rr * 128 + ((c ^ (rr & 7)) << 4),
                          Bb + (long)rr * p.ldb + kt * 64 + c * 8);
                }
            }
        }
        CP_COMMIT();
    };

    const int la = lane & 7;
    const int ksegA = (lane >> 4) & 1;
    const int ksegB = (lane >> 3) & 1;
    int aRow[MT], aSw[MT], bRow[NTj / 2], bSw[NTj / 2];
#pragma unroll
    for (int i = 0; i < MT; i++) {
        int r = wm * WTM + i * 16 + ((lane >> 3) & 1) * 8 + la;
        aRow[i] = r * 128;
        aSw[i]  = r & 7;
    }
#pragma unroll
    for (int j = 0; j < NTj / 2; j++) {
        int r = wn * WTN + j * 16 + ((lane >> 4) & 1) * 8 + la;
        bRow[j] = r * 128;
        bSw[j]  = r & 7;
    }

    float acc[MT][NTj][4];
#pragma unroll
    for (int i = 0; i < MT; i++)
#pragma unroll
        for (int j = 0; j < NTj; j++)
#pragma unroll
            for (int k = 0; k < 4; k++) acc[i][j][k] = 0.f;

#pragma unroll
    for (int s = 0; s < STAGES - 1; s++) loadStage(s);

    for (int kt = 0; kt < KT; kt++) {
        asm volatile("cp.async.wait_group %0;" :: "n"(STAGES - 2));
        __syncthreads();
        loadStage(kt + STAGES - 1);

        const u32 sA = sb + (kt % STAGES) * STGB;
        const u32 sB = sA + BM * 128;
#pragma unroll
        for (int ks = 0; ks < 4; ks++) {
            u32 af[MT][4], bf[NTj][2];
            const int ca = ks * 2 + ksegA;
            const int cb = ks * 2 + ksegB;
#pragma unroll
            for (int i = 0; i < MT; i++)
                ldsm4(af[i][0], af[i][1], af[i][2], af[i][3],
                      sA + aRow[i] + ((ca ^ aSw[i]) << 4));
#pragma unroll
            for (int j = 0; j < NTj / 2; j++)
                ldsm4(bf[2 * j][0], bf[2 * j][1], bf[2 * j + 1][0], bf[2 * j + 1][1],
                      sB + bRow[j] + ((cb ^ bSw[j]) << 4));
#pragma unroll
            for (int i = 0; i < MT; i++)
#pragma unroll
                for (int j = 0; j < NTj; j++)
                    mma16(acc[i][j], af[i], bf[j]);
        }
    }

    // ---------------- epilogue ----------------
    const long row0 = (long)blockIdx.y * BM + wm * WTM;
    const long col0 = (long)blockIdx.x * BN + wn * WTN;

#pragma unroll
    for (int i = 0; i < MT; i++) {
        const long r0 = row0 + i * 16 + g;
#pragma unroll
        for (int j = 0; j < NTj; j++) {
            const long c = col0 + j * 8 + tg * 2;
            float v0 = acc[i][j][0], v1 = acc[i][j][1];
            float v2 = acc[i][j][2], v3 = acc[i][j][3];
            if constexpr (EPI == 4) {
                float b0 = p.bias[c], b1 = p.bias[c + 1];
                v0 += b0; v1 += b1; v2 += b0; v3 += b1;
                float* C = (float*)p.C + (long)b * p.Cb + (long)h * p.Ch;
                *(float2*)(C + r0 * p.ldc + c)       = make_float2(v0, v1);
                *(float2*)(C + (r0 + 8) * p.ldc + c) = make_float2(v2, v3);
            } else if constexpr (EPI == 2) {
                const u32* mb = p.mask + (long)b * p.maskB;
                const int  wofs = (int)(c >> 5), sh = (int)(c & 31);
                u32 w0 = mb[r0 * (S_ / 32) + wofs];
                u32 w1 = mb[(r0 + 8) * (S_ / 32) + wofs];
                v0 = (w0 >> sh) & 1       ? v0 * p.scale : 0.f;
                v1 = (w0 >> (sh + 1)) & 1 ? v1 * p.scale : 0.f;
                v2 = (w1 >> sh) & 1       ? v2 * p.scale : 0.f;
                v3 = (w1 >> (sh + 1)) & 1 ? v3 * p.scale : 0.f;
                __half* C = (__half*)p.C + (long)b * p.Cb + (long)h * p.Ch;
                *(__half2*)(C + r0 * p.ldc + c)       = __floats2half2_rn(v0, v1);
                *(__half2*)(C + (r0 + 8) * p.ldc + c) = __floats2half2_rn(v2, v3);
            } else if constexpr (EPI == 5) {
                const float* bs = (z == 0) ? p.bias : (z == 1) ? p.bias1 : p.bias2;
                float b0 = bs[c], b1 = bs[c + 1];
                v0 += b0; v1 += b1; v2 += b0; v3 += b1;
                if (z == 2) {
                    __half* Ct = (__half*)p.C2;
                    const int hh = (int)(c >> 6), d = (int)(c & 63);
                    {
                        const long bb = r0 >> 11, s = r0 & (S_ - 1);
                        __half* base = Ct + ((bb * H_ + hh) * 64 + d) * (long)S_ + s;
                        base[0]  = __float2half_rn(v0);
                        base[S_] = __float2half_rn(v1);
                    }
                    {
                        const long bb = (r0 + 8) >> 11, s = (r0 + 8) & (S_ - 1);
                        __half* base = Ct + ((bb * H_ + hh) * 64 + d) * (long)S_ + s;
                        base[0]  = __float2half_rn(v2);
                        base[S_] = __float2half_rn(v3);
                    }
                } else {
                    __half* C = (__half*)(z == 0 ? p.C : p.C1);
                    *(__half2*)(C + r0 * p.ldc + c)       = __floats2half2_rn(v0, v1);
                    *(__half2*)(C + (r0 + 8) * p.ldc + c) = __floats2half2_rn(v2, v3);
                }
            } else {
                __half* C = (__half*)p.C + (long)b * p.Cb + (long)h * p.Ch;
                *(__half2*)(C + r0 * p.ldc + c)       = __floats2half2_rn(v0, v1);
                *(__half2*)(C + (r0 + 8) * p.ldc + c) = __floats2half2_rn(v2, v3);
            }
        }
    }
}

// ---------------- mask bitpack ----------------
__global__ __launch_bounds__(256) void pack_k(const int* __restrict__ mask,
                                              u32* __restrict__ out) {
    const long i = (long)blockIdx.x * 256 + threadIdx.x;
    const int  m = mask[i];
    const u32  w = __ballot_sync(0xffffffffu, m != 0);
    if ((threadIdx.x & 31) == 0) out[i >> 5] = w;
}

// ---------------- batched fp32 -> fp16 converts (3 inputs, z-indexed) --------
struct CV { const float4* in[4]; uint2* out[4]; };
__global__ __launch_bounds__(256) void cvt3_k(CV cp) {
    const int z = blockIdx.z;
    long i = (long)blockIdx.x * 256 + threadIdx.x;
    float4 v = cp.in[z][i];
    __half2 lo = __floats2half2_rn(v.x, v.y);
    __half2 hi = __floats2half2_rn(v.z, v.w);
    cp.out[z][i] = make_uint2(*(u32*)&lo, *(u32*)&hi);
}

// ---------------- single fp32 -> fp16 convert (P matrix) ----------
__global__ __launch_bounds__(256) void cvt1_k(const float4* __restrict__ in,
                                              uint2* __restrict__ out) {
    long i = (long)blockIdx.x * 256 + threadIdx.x;
    float4 v = in[i];
    __half2 lo = __floats2half2_rn(v.x, v.y);
    __half2 hi = __floats2half2_rn(v.z, v.w);
    out[i] = make_uint2(*(u32*)&lo, *(u32*)&hi);
}

// ---------------- batched weight transposes (z-indexed) ----------
struct TR { const float* in[4]; __half* out[4]; };
__global__ __launch_bounds__(256) void tr4_k(TR tp) {
    __shared__ float t[32][33];
    const int z = blockIdx.z;
    const float* in = tp.in[z];
    __half* out = tp.out[z];
    const int bx = blockIdx.x * 32, by = blockIdx.y * 32;
    const int x = threadIdx.x & 31, y0 = (threadIdx.x >> 5) * 4;
#pragma unroll
    for (int i = 0; i < 4; i++)
        t[y0 + i][x] = in[(long)(by + y0 + i) * D_ + bx + x];
    __syncthreads();
#pragma unroll
    for (int i = 0; i < 4; i++)
        out[(long)(bx + y0 + i) * D_ + by + x] = __float2half_rn(t[x][y0 + i]);
}

// ---------------- masked softmax + nan_to_num, fp16 in-place, bit mask -------
__global__ __launch_bounds__(256) void softmax_h(__half* __restrict__ S,
                                                 const u32* __restrict__ maskb) {
    const long r  = blockIdx.x;                 // [0, B*H*S)
    const int  q  = (int)(r & (S_ - 1));
    const int  bh = (int)(r >> 11);
    const int  b  = bh >> 4;
    __half* row = S + r * (long)S_;
    const u32* mrow = maskb + ((long)b * S_ + q) * (S_ / 32);
    const int tid = threadIdx.x;

    uint4 xr = ((const uint4*)row)[tid];        // 8 halves
    const u32 mw    = mrow[tid >> 2];
    const u32 mbits = (mw >> ((tid & 3) * 8)) & 0xFFu;
    const __half2* hp = (const __half2*)&xr;
    float xs[8];
#pragma unroll
    for (int i = 0; i < 4; i++) {
        float2 f = __half22float2(hp[i]);
        xs[i * 2] = f.x; xs[i * 2 + 1] = f.y;
    }

    float lmax = -3.402823466e38f;
#pragma unroll
    for (int i = 0; i < 8; i++)
        if ((mbits >> i) & 1) lmax = fmaxf(lmax, xs[i]);
#pragma unroll
    for (int o = 16; o > 0; o >>= 1)
        lmax = fmaxf(lmax, __shfl_xor_sync(0xffffffffu, lmax, o));

    __shared__ float sm[8];
    if ((tid & 31) == 0) sm[tid >> 5] = lmax;
    __syncthreads();
    float bmax = sm[0];
#pragma unroll
    for (int i = 1; i < 8; i++) bmax = fmaxf(bmax, sm[i]);
    __syncthreads();

    float es[8];
    float lsum = 0.f;
#pragma unroll
    for (int i = 0; i < 8; i++) {
        es[i] = ((mbits >> i) & 1) ? expf(xs[i] - bmax) : 0.f;
        lsum += es[i];
    }
#pragma unroll
    for (int o = 16; o > 0; o >>= 1)
        lsum += __shfl_xor_sync(0xffffffffu, lsum, o);
    if ((tid & 31) == 0) sm[tid >> 5] = lsum;
    __syncthreads();
    float bsum = 0.f;
#pragma unroll
    for (int i = 0; i < 8; i++) bsum += sm[i];

    const float inv = (bsum > 0.f) ? 1.f / bsum : 0.f;
    uint4 outr;
    __half2* op = (__half2*)&outr;
#pragma unroll
    for (int i = 0; i < 4; i++)
        op[i] = __floats2half2_rn(es[i * 2] * inv, es[i * 2 + 1] * inv);
    ((uint4*)row)[tid] = outr;
}

// ---------------- launch ----------------
#define SMEM_BIG (4 * (128 + 256) * 128)   // 196608 (prop)
#define SMEM_QK  (2 * (128 + 128) * 128)   //  65536
#define SMEM_PRJ (3 * (128 + 128) * 128)   //  98304 (proj / Wo, 2 CTAs/SM)
#define SMEM_AV  (4 * (128 + 64) * 128)    //  98304

extern "C" void kernel_launch(void* const* d_in, const int* in_sizes, int n_in,
                              void* d_out, int out_size) {
    (void)in_sizes; (void)n_in; (void)out_size;
    const float* inq  = (const float*)d_in[0];
    const float* ink  = (const float*)d_in[1];
    const float* invv = (const float*)d_in[2];
    const int*   mask = (const int*)d_in[3];
    const float* prop = (const float*)d_in[4];
    const float* Wq = (const float*)d_in[5];
    const float* bq = (const float*)d_in[6];
    const float* Wk = (const float*)d_in[7];
    const float* bk = (const float*)d_in[8];
    const float* Wv = (const float*)d_in[9];
    const float* bv = (const float*)d_in[10];
    const float* Wo = (const float*)d_in[11];
    const float* bo = (const float*)d_in[12];

    __half *Xq, *Xk, *Xv, *Qh, *Kh, *Vt, *Oh, *Ph, *Wqt, *Wkt, *Wvt, *Wot, *S1, *S2;
    u32* Mb;
    cudaGetSymbolAddress((void**)&Xq, g_Xq);
    cudaGetSymbolAddress((void**)&Xk, g_Xk);
    cudaGetSymbolAddress((void**)&Xv, g_Xv);
    cudaGetSymbolAddress((void**)&Qh, g_Qh);
    cudaGetSymbolAddress((void**)&Kh, g_Kh);
    cudaGetSymbolAddress((void**)&Vt, g_Vt);
    cudaGetSymbolAddress((void**)&Oh, g_Oh);
    cudaGetSymbolAddress((void**)&Ph, g_Ph);
    cudaGetSymbolAddress((void**)&Wqt, g_Wqt);
    cudaGetSymbolAddress((void**)&Wkt, g_Wkt);
    cudaGetSymbolAddress((void**)&Wvt, g_Wvt);
    cudaGetSymbolAddress((void**)&Wot, g_Wot);
    cudaGetSymbolAddress((void**)&S1, g_S1);
    cudaGetSymbolAddress((void**)&S2, g_S2);
    cudaGetSymbolAddress((void**)&Mb, g_Mb);

    cudaFuncSetAttribute((gemm_l<128, 128, 2, 4, 5, 3, 2>), cudaFuncAttributeMaxDynamicSharedMemorySize, SMEM_PRJ);
    cudaFuncSetAttribute((gemm_l<128, 128, 2, 4, 2, 2, 2>), cudaFuncAttributeMaxDynamicSharedMemorySize, SMEM_QK);
    cudaFuncSetAttribute((gemm_l<128, 256, 2, 4, 0, 4>),    cudaFuncAttributeMaxDynamicSharedMemorySize, SMEM_BIG);
    cudaFuncSetAttribute((gemm_l<128, 128, 2, 4, 4, 3, 2>), cudaFuncAttributeMaxDynamicSharedMemorySize, SMEM_PRJ);
    cudaFuncSetAttribute((gemm_l<128, 64, 4, 2, 0, 4, 2>),  cudaFuncAttributeMaxDynamicSharedMemorySize, SMEM_AV);

    // side stream + events (capture-safe fork/join, verified in R13/R15)
    cudaStream_t sB;
    cudaStreamCreateWithFlags(&sB, cudaStreamNonBlocking);
    cudaEvent_t eFork, ePrep;
    cudaEventCreateWithFlags(&eFork, cudaEventDisableTiming);
    cudaEventCreateWithFlags(&ePrep, cudaEventDisableTiming);

    dim3 blk(256);

    // fork point: sB starts at capture origin
    cudaEventRecord(eFork, 0);
    cudaStreamWaitEvent(sB, eFork, 0);

    // ---- sB: mask bitpack + P convert + Wo transpose (not needed until later) ----
    pack_k<<<(int)(((long)B_ * S_ * S_) / 256), blk, 0, sB>>>(mask, Mb);
    cvt1_k<<<(int)(((long)S_ * S_) / 1024), blk, 0, sB>>>((const float4*)prop, (uint2*)Ph);
    {
        TR tw;
        tw.in[0] = Wo; tw.out[0] = Wot;
        tw.in[1] = Wo; tw.out[1] = Wot;   // unused z<1
        tw.in[2] = Wo; tw.out[2] = Wot;
        tw.in[3] = Wo; tw.out[3] = Wot;
        tr4_k<<<dim3(D_ / 32, D_ / 32, 1), blk, 0, sB>>>(tw);
    }
    cudaEventRecord(ePrep, sB);

    // ---- s0: input converts + Q/K/V weight transposes (needed by projections) ----
    {
        CV cp;
        cp.in[0] = (const float4*)inq;  cp.out[0] = (uint2*)Xq;
        cp.in[1] = (const float4*)ink;  cp.out[1] = (uint2*)Xk;
        cp.in[2] = (const float4*)invv; cp.out[2] = (uint2*)Xv;
        cp.in[3] = (const float4*)inq;  cp.out[3] = (uint2*)Xq;   // unused z<3
        cvt3_k<<<dim3(4096, 1, 3), blk>>>(cp);
        TR tp;
        tp.in[0] = Wq; tp.out[0] = Wqt;
        tp.in[1] = Wk; tp.out[1] = Wkt;
        tp.in[2] = Wv; tp.out[2] = Wvt;
        tp.in[3] = Wq; tp.out[3] = Wqt;   // unused z<3
        tr4_k<<<dim3(D_ / 32, D_ / 32, 3), blk>>>(tp);
    }

    // 1: all three projections in one launch (z = 0:Q, 1:K, 2:V-transposed)
    //    128x128 tile, 3 stages, 2 CTAs/SM (latency-bound kernel: more CTAs win)
    {
        HP p{};
        p.lda = D_; p.ldb = D_; p.ldc = D_;
        p.K = D_;
        p.A  = Xq; p.Bm  = Wqt; p.C  = Qh; p.bias  = bq;
        p.A1 = Xk; p.Bm1 = Wkt; p.C1 = Kh; p.bias1 = bk;
        p.A2 = Xv; p.Bm2 = Wvt; p.C2 = Vt; p.bias2 = bv;
        dim3 grid(D_ / 128, (B_ * S_) / 128, 3);
        gemm_l<128, 128, 2, 4, 5, 3, 2><<<grid, blk, SMEM_PRJ>>>(p);
    }

    // join: mask bits + Ph + Wot ready before QK^T / prop / Wo
    cudaStreamWaitEvent(0, ePrep, 0);

    // 2: S1 = maskbit ? (Q.K^T)/8 : 0   (batched NT, K=64; 128x128, 2 CTAs/SM)
    {
        HP p{};
        p.A = Qh; p.lda = D_; p.Ab = (long)S_ * D_; p.Ah = DK_;
        p.Bm = Kh; p.ldb = D_; p.Bb = (long)S_ * D_; p.Bh = DK_;
        p.C = S1; p.ldc = S_; p.Cb = (long)H_ * S_ * S_; p.Ch = (long)S_ * S_;
        p.mask = Mb; p.maskB = (long)S_ * S_ / 32;
        p.scale = 0.125f;
        p.K = DK_;
        dim3 grid(S_ / 128, S_ / 128, B_ * H_);
        gemm_l<128, 128, 2, 4, 2, 2, 2><<<grid, blk, SMEM_QK>>>(p);
    }

    // 3: S2 = S1 @ P^T   (batched NT, K=2048 — tensor-roofline GEMM)
    {
        HP p{};
        p.A = S1; p.lda = S_; p.Ab = (long)H_ * S_ * S_; p.Ah = (long)S_ * S_;
        p.Bm = Ph; p.ldb = S_;
        p.C = S2; p.ldc = S_; p.Cb = (long)H_ * S_ * S_; p.Ch = (long)S_ * S_;
        p.K = S_;
        dim3 grid(S_ / 256, S_ / 128, B_ * H_);
        gemm_l<128, 256, 2, 4, 0, 4><<<grid, blk, SMEM_BIG>>>(p);
    }

    // 4: masked softmax + nan_to_num (in place, fp16, bit mask)
    softmax_h<<<B_ * H_ * S_, blk>>>(S2, Mb);

    // 5: Oh = probs @ V   (batched NT vs Vt, N=64, K=2048; 2 CTAs/SM)
    {
        HP p{};
        p.A = S2; p.lda = S_; p.Ab = (long)H_ * S_ * S_; p.Ah = (long)S_ * S_;
        p.Bm = Vt; p.ldb = S_; p.Bb = (long)H_ * DK_ * S_; p.Bh = (long)DK_ * S_;
        p.C = Oh; p.ldc = D_; p.Cb = (long)S_ * D_; p.Ch = DK_;
        p.K = S_;
        dim3 grid(1, S_ / 128, B_ * H_);
        gemm_l<128, 64, 4, 2, 0, 4, 2><<<grid, blk, SMEM_AV>>>(p);
    }

    // 6: out = Oh @ Wo + bo   (NT, fp32 store; 128x128, 2 CTAs/SM)
    {
        HP p{};
        p.A = Oh; p.lda = D_;
        p.Bm = Wot; p.ldb = D_;
        p.bias = bo;
        p.C = d_out; p.ldc = D_;
        p.K = D_;
        dim3 grid(D_ / 128, (B_ * S_) / 128, 1);
        gemm_l<128, 128, 2, 4, 4, 3, 2><<<grid, blk, SMEM_PRJ>>>(p);
    }
}

// round 17
// speedup vs baseline: 1.0791x; 1.0064x over previous
#include <cuda_runtime.h>
#include <cuda_fp16.h>
#include <cstdint>

#define B_  2
#define S_  2048
#define D_  1024
#define H_  16
#define DK_ 64

typedef unsigned int u32;

// ---------------- scratch (device globals: allocation-free) ----------------
__device__ __half g_Xq[(size_t)B_ * S_ * D_];
__device__ __half g_Xk[(size_t)B_ * S_ * D_];
__device__ __half g_Xv[(size_t)B_ * S_ * D_];
__device__ __half g_Qh[(size_t)B_ * S_ * D_];
__device__ __half g_Kh[(size_t)B_ * S_ * D_];
__device__ __half g_Vt[(size_t)B_ * S_ * D_];      // V transposed [b][h][dk][S]
__device__ __half g_Oh[(size_t)B_ * S_ * D_];
__device__ __half g_Ph[(size_t)S_ * S_];
__device__ __half g_Wqt[(size_t)D_ * D_];
__device__ __half g_Wkt[(size_t)D_ * D_];
__device__ __half g_Wvt[(size_t)D_ * D_];
__device__ __half g_Wot[(size_t)D_ * D_];
__device__ __half g_S1[(size_t)B_ * H_ * S_ * S_]; // 256 MB
__device__ __half g_S2[(size_t)B_ * H_ * S_ * S_]; // 256 MB
__device__ u32    g_Mb[(size_t)B_ * S_ * S_ / 32]; // bitpacked mask (1 MB)

// ---------------- asm helpers ----------------
__device__ __forceinline__ void mma16(float* c, const u32* a, const u32* b) {
    asm volatile(
        "mma.sync.aligned.m16n8k16.row.col.f32.f16.f16.f32 "
        "{%0,%1,%2,%3},{%4,%5,%6,%7},{%8,%9},{%0,%1,%2,%3};\n"
        : "+f"(c[0]), "+f"(c[1]), "+f"(c[2]), "+f"(c[3])
        : "r"(a[0]), "r"(a[1]), "r"(a[2]), "r"(a[3]), "r"(b[0]), "r"(b[1]));
}

__device__ __forceinline__ void ldsm4(u32& r0, u32& r1, u32& r2, u32& r3, u32 a) {
    asm volatile("ldmatrix.sync.aligned.m8n8.x4.shared.b16 {%0,%1,%2,%3}, [%4];"
                 : "=r"(r0), "=r"(r1), "=r"(r2), "=r"(r3) : "r"(a));
}

__device__ __forceinline__ u32 smem_u32(const void* p) {
    u32 a;
    asm("{ .reg .u64 t; cvta.to.shared.u64 t, %1; cvt.u32.u64 %0, t; }"
        : "=r"(a) : "l"(p));
    return a;
}

__device__ __forceinline__ void cpa16(u32 dst, const void* src) {
    asm volatile("cp.async.cg.shared.global [%0], [%1], 16;" :: "r"(dst), "l"(src));
}
#define CP_COMMIT() asm volatile("cp.async.commit_group;" ::: "memory")

struct HP {
    const __half* A;
    const __half* Bm;
    void*         C;
    const float*  bias;
    const u32*    mask;       // bitpacked
    const __half *A1, *A2, *Bm1, *Bm2;   // EPI5 (triple projection)
    void *C1, *C2;
    const float *bias1, *bias2;
    long lda, ldb, ldc;
    long Ab, Ah, Bb, Bh, Cb, Ch, maskB;
    float scale;
    int  K;
};

// ---------------- fp16 NT GEMM template ----------------
// EPI: 0 plain fp16, 2 maskbit?v*scale:0 fp16, 4 +bias fp32,
//      5 triple-projection (z selects operands; z==2 stores transposed V)
template<int BM, int BN, int WMN, int WNN, int EPI, int STAGES, int MINB = 1>
__global__ __launch_bounds__(256, MINB) void gemm_l(HP p) {
    static_assert(WMN * WNN == 8, "8 warps");
    constexpr int WTM  = BM / WMN;
    constexpr int WTN  = BN / WNN;
    constexpr int MT   = WTM / 16;
    constexpr int NTj  = WTN / 8;
    constexpr int STGB = (BM + BN) * 128;
    constexpr int CHK  = (BM + BN) * 8 / 256;

    extern __shared__ __align__(1024) char smem[];
    const u32 sb = smem_u32(smem);

    const int tid  = threadIdx.x;
    const int wid  = tid >> 5, lane = tid & 31;
    const int wm   = wid / WNN, wn = wid % WNN;
    const int g    = lane >> 2, tg = lane & 3;
    const int z    = blockIdx.z;
    const int b    = z / H_, h = z % H_;

    const __half *Abase, *Bbase;
    if constexpr (EPI == 5) {
        Abase = (z == 0) ? p.A : (z == 1) ? p.A1 : p.A2;
        Bbase = (z == 0) ? p.Bm : (z == 1) ? p.Bm1 : p.Bm2;
    } else {
        Abase = p.A + (long)b * p.Ab + (long)h * p.Ah;
        Bbase = p.Bm + (long)b * p.Bb + (long)h * p.Bh;
    }
    const __half* Ab = Abase + (long)blockIdx.y * BM * p.lda;
    const __half* Bb = Bbase + (long)blockIdx.x * BN * p.ldb;

    const int KT = p.K >> 6;

    int cR[CHK], cC[CHK];
#pragma unroll
    for (int i = 0; i < CHK; i++) {
        int id = tid + i * 256;
        cR[i] = id >> 3;
        cC[i] = id & 7;
    }

    auto loadStage = [&](int kt) {
        if (kt < KT) {
            const u32 s0 = sb + (kt % STAGES) * STGB;
#pragma unroll
            for (int i = 0; i < CHK; i++) {
                int r = cR[i], c = cC[i];
                if (r < BM) {
                    cpa16(s0 + r * 128 + ((c ^ (r & 7)) << 4),
                          Ab + (long)r * p.lda + kt * 64 + c * 8);
                } else {
                    int rr = r - BM;
                    cpa16(s0 + BM * 128 + rr * 128 + ((c ^ (rr & 7)) << 4),
                          Bb + (long)rr * p.ldb + kt * 64 + c * 8);
                }
            }
        }
        CP_COMMIT();
    };

    const int la = lane & 7;
    const int ksegA = (lane >> 4) & 1;
    const int ksegB = (lane >> 3) & 1;
    int aRow[MT], aSw[MT], bRow[NTj / 2], bSw[NTj / 2];
#pragma unroll
    for (int i = 0; i < MT; i++) {
        int r = wm * WTM + i * 16 + ((lane >> 3) & 1) * 8 + la;
        aRow[i] = r * 128;
        aSw[i]  = r & 7;
    }
#pragma unroll
    for (int j = 0; j < NTj / 2; j++) {
        int r = wn * WTN + j * 16 + ((lane >> 4) & 1) * 8 + la;
        bRow[j] = r * 128;
        bSw[j]  = r & 7;
    }

    float acc[MT][NTj][4];
#pragma unroll
    for (int i = 0; i < MT; i++)
#pragma unroll
        for (int j = 0; j < NTj; j++)
#pragma unroll
            for (int k = 0; k < 4; k++) acc[i][j][k] = 0.f;

#pragma unroll
    for (int s = 0; s < STAGES - 1; s++) loadStage(s);

    for (int kt = 0; kt < KT; kt++) {
        asm volatile("cp.async.wait_group %0;" :: "n"(STAGES - 2));
        __syncthreads();
        loadStage(kt + STAGES - 1);

        const u32 sA = sb + (kt % STAGES) * STGB;
        const u32 sB = sA + BM * 128;
#pragma unroll
        for (int ks = 0; ks < 4; ks++) {
            u32 af[MT][4], bf[NTj][2];
            const int ca = ks * 2 + ksegA;
            const int cb = ks * 2 + ksegB;
#pragma unroll
            for (int i = 0; i < MT; i++)
                ldsm4(af[i][0], af[i][1], af[i][2], af[i][3],
                      sA + aRow[i] + ((ca ^ aSw[i]) << 4));
#pragma unroll
            for (int j = 0; j < NTj / 2; j++)
                ldsm4(bf[2 * j][0], bf[2 * j][1], bf[2 * j + 1][0], bf[2 * j + 1][1],
                      sB + bRow[j] + ((cb ^ bSw[j]) << 4));
#pragma unroll
            for (int i = 0; i < MT; i++)
#pragma unroll
                for (int j = 0; j < NTj; j++)
                    mma16(acc[i][j], af[i], bf[j]);
        }
    }

    // ---------------- epilogue ----------------
    const long row0 = (long)blockIdx.y * BM + wm * WTM;
    const long col0 = (long)blockIdx.x * BN + wn * WTN;

#pragma unroll
    for (int i = 0; i < MT; i++) {
        const long r0 = row0 + i * 16 + g;
#pragma unroll
        for (int j = 0; j < NTj; j++) {
            const long c = col0 + j * 8 + tg * 2;
            float v0 = acc[i][j][0], v1 = acc[i][j][1];
            float v2 = acc[i][j][2], v3 = acc[i][j][3];
            if constexpr (EPI == 4) {
                float b0 = p.bias[c], b1 = p.bias[c + 1];
                v0 += b0; v1 += b1; v2 += b0; v3 += b1;
                float* C = (float*)p.C + (long)b * p.Cb + (long)h * p.Ch;
                *(float2*)(C + r0 * p.ldc + c)       = make_float2(v0, v1);
                *(float2*)(C + (r0 + 8) * p.ldc + c) = make_float2(v2, v3);
            } else if constexpr (EPI == 2) {
                const u32* mb = p.mask + (long)b * p.maskB;
                const int  wofs = (int)(c >> 5), sh = (int)(c & 31);
                u32 w0 = mb[r0 * (S_ / 32) + wofs];
                u32 w1 = mb[(r0 + 8) * (S_ / 32) + wofs];
                v0 = (w0 >> sh) & 1       ? v0 * p.scale : 0.f;
                v1 = (w0 >> (sh + 1)) & 1 ? v1 * p.scale : 0.f;
                v2 = (w1 >> sh) & 1       ? v2 * p.scale : 0.f;
                v3 = (w1 >> (sh + 1)) & 1 ? v3 * p.scale : 0.f;
                __half* C = (__half*)p.C + (long)b * p.Cb + (long)h * p.Ch;
                *(__half2*)(C + r0 * p.ldc + c)       = __floats2half2_rn(v0, v1);
                *(__half2*)(C + (r0 + 8) * p.ldc + c) = __floats2half2_rn(v2, v3);
            } else if constexpr (EPI == 5) {
                const float* bs = (z == 0) ? p.bias : (z == 1) ? p.bias1 : p.bias2;
                float b0 = bs[c], b1 = bs[c + 1];
                v0 += b0; v1 += b1; v2 += b0; v3 += b1;
                if (z == 2) {
                    __half* Ct = (__half*)p.C2;
                    const int hh = (int)(c >> 6), d = (int)(c & 63);
                    {
                        const long bb = r0 >> 11, s = r0 & (S_ - 1);
                        __half* base = Ct + ((bb * H_ + hh) * 64 + d) * (long)S_ + s;
                        base[0]  = __float2half_rn(v0);
                        base[S_] = __float2half_rn(v1);
                    }
                    {
                        const long bb = (r0 + 8) >> 11, s = (r0 + 8) & (S_ - 1);
                        __half* base = Ct + ((bb * H_ + hh) * 64 + d) * (long)S_ + s;
                        base[0]  = __float2half_rn(v2);
                        base[S_] = __float2half_rn(v3);
                    }
                } else {
                    __half* C = (__half*)(z == 0 ? p.C : p.C1);
                    *(__half2*)(C + r0 * p.ldc + c)       = __floats2half2_rn(v0, v1);
                    *(__half2*)(C + (r0 + 8) * p.ldc + c) = __floats2half2_rn(v2, v3);
                }
            } else {
                __half* C = (__half*)p.C + (long)b * p.Cb + (long)h * p.Ch;
                *(__half2*)(C + r0 * p.ldc + c)       = __floats2half2_rn(v0, v1);
                *(__half2*)(C + (r0 + 8) * p.ldc + c) = __floats2half2_rn(v2, v3);
            }
        }
    }
}

// ---------------- mask bitpack ----------------
__global__ __launch_bounds__(256) void pack_k(const int* __restrict__ mask,
                                              u32* __restrict__ out) {
    const long i = (long)blockIdx.x * 256 + threadIdx.x;
    const int  m = mask[i];
    const u32  w = __ballot_sync(0xffffffffu, m != 0);
    if ((threadIdx.x & 31) == 0) out[i >> 5] = w;
}

// ---------------- batched fp32 -> fp16 converts (3 inputs, 2 float4/thread) --
struct CV { const float4* in[4]; uint2* out[4]; };
__global__ __launch_bounds__(256) void cvt3_k(CV cp) {
    const int z = blockIdx.z;
    const long i0 = (long)blockIdx.x * 512 + threadIdx.x;
    float4 v0 = cp.in[z][i0];
    float4 v1 = cp.in[z][i0 + 256];
    __half2 a0 = __floats2half2_rn(v0.x, v0.y);
    __half2 a1 = __floats2half2_rn(v0.z, v0.w);
    __half2 b0 = __floats2half2_rn(v1.x, v1.y);
    __half2 b1 = __floats2half2_rn(v1.z, v1.w);
    cp.out[z][i0]       = make_uint2(*(u32*)&a0, *(u32*)&a1);
    cp.out[z][i0 + 256] = make_uint2(*(u32*)&b0, *(u32*)&b1);
}

// ---------------- single fp32 -> fp16 convert (P matrix) ----------
__global__ __launch_bounds__(256) void cvt1_k(const float4* __restrict__ in,
                                              uint2* __restrict__ out) {
    long i = (long)blockIdx.x * 256 + threadIdx.x;
    float4 v = in[i];
    __half2 lo = __floats2half2_rn(v.x, v.y);
    __half2 hi = __floats2half2_rn(v.z, v.w);
    out[i] = make_uint2(*(u32*)&lo, *(u32*)&hi);
}

// ---------------- batched weight transposes (z-indexed) ----------
struct TR { const float* in[4]; __half* out[4]; };
__global__ __launch_bounds__(256) void tr4_k(TR tp) {
    __shared__ float t[32][33];
    const int z = blockIdx.z;
    const float* in = tp.in[z];
    __half* out = tp.out[z];
    const int bx = blockIdx.x * 32, by = blockIdx.y * 32;
    const int x = threadIdx.x & 31, y0 = (threadIdx.x >> 5) * 4;
#pragma unroll
    for (int i = 0; i < 4; i++)
        t[y0 + i][x] = in[(long)(by + y0 + i) * D_ + bx + x];
    __syncthreads();
#pragma unroll
    for (int i = 0; i < 4; i++)
        out[(long)(bx + y0 + i) * D_ + by + x] = __float2half_rn(t[x][y0 + i]);
}

// ---------------- masked softmax + nan_to_num, fp16 in-place, bit mask -------
__global__ __launch_bounds__(256) void softmax_h(__half* __restrict__ S,
                                                 const u32* __restrict__ maskb) {
    const long r  = blockIdx.x;                 // [0, B*H*S)
    const int  q  = (int)(r & (S_ - 1));
    const int  bh = (int)(r >> 11);
    const int  b  = bh >> 4;
    __half* row = S + r * (long)S_;
    const u32* mrow = maskb + ((long)b * S_ + q) * (S_ / 32);
    const int tid = threadIdx.x;

    uint4 xr = ((const uint4*)row)[tid];        // 8 halves
    const u32 mw    = mrow[tid >> 2];
    const u32 mbits = (mw >> ((tid & 3) * 8)) & 0xFFu;
    const __half2* hp = (const __half2*)&xr;
    float xs[8];
#pragma unroll
    for (int i = 0; i < 4; i++) {
        float2 f = __half22float2(hp[i]);
        xs[i * 2] = f.x; xs[i * 2 + 1] = f.y;
    }

    float lmax = -3.402823466e38f;
#pragma unroll
    for (int i = 0; i < 8; i++)
        if ((mbits >> i) & 1) lmax = fmaxf(lmax, xs[i]);
#pragma unroll
    for (int o = 16; o > 0; o >>= 1)
        lmax = fmaxf(lmax, __shfl_xor_sync(0xffffffffu, lmax, o));

    __shared__ float sm[8];
    if ((tid & 31) == 0) sm[tid >> 5] = lmax;
    __syncthreads();
    float bmax = sm[0];
#pragma unroll
    for (int i = 1; i < 8; i++) bmax = fmaxf(bmax, sm[i]);
    __syncthreads();

    float es[8];
    float lsum = 0.f;
#pragma unroll
    for (int i = 0; i < 8; i++) {
        es[i] = ((mbits >> i) & 1) ? expf(xs[i] - bmax) : 0.f;
        lsum += es[i];
    }
#pragma unroll
    for (int o = 16; o > 0; o >>= 1)
        lsum += __shfl_xor_sync(0xffffffffu, lsum, o);
    if ((tid & 31) == 0) sm[tid >> 5] = lsum;
    __syncthreads();
    float bsum = 0.f;
#pragma unroll
    for (int i = 0; i < 8; i++) bsum += sm[i];

    const float inv = (bsum > 0.f) ? 1.f / bsum : 0.f;
    uint4 outr;
    __half2* op = (__half2*)&outr;
#pragma unroll
    for (int i = 0; i < 4; i++)
        op[i] = __floats2half2_rn(es[i * 2] * inv, es[i * 2 + 1] * inv);
    ((uint4*)row)[tid] = outr;
}

// ---------------- launch ----------------
#define SMEM_BIG (4 * (128 + 256) * 128)   // 196608 (prop)
#define SMEM_QK  (2 * (128 + 128) * 128)   //  65536
#define SMEM_PRJ (3 * (128 + 128) * 128)   //  98304 (proj / Wo, 2 CTAs/SM)
#define SMEM_AV  (4 * (64 + 64) * 128)     //  65536 (AV, 3 CTAs/SM)

extern "C" void kernel_launch(void* const* d_in, const int* in_sizes, int n_in,
                              void* d_out, int out_size) {
    (void)in_sizes; (void)n_in; (void)out_size;
    const float* inq  = (const float*)d_in[0];
    const float* ink  = (const float*)d_in[1];
    const float* invv = (const float*)d_in[2];
    const int*   mask = (const int*)d_in[3];
    const float* prop = (const float*)d_in[4];
    const float* Wq = (const float*)d_in[5];
    const float* bq = (const float*)d_in[6];
    const float* Wk = (const float*)d_in[7];
    const float* bk = (const float*)d_in[8];
    const float* Wv = (const float*)d_in[9];
    const float* bv = (const float*)d_in[10];
    const float* Wo = (const float*)d_in[11];
    const float* bo = (const float*)d_in[12];

    __half *Xq, *Xk, *Xv, *Qh, *Kh, *Vt, *Oh, *Ph, *Wqt, *Wkt, *Wvt, *Wot, *S1, *S2;
    u32* Mb;
    cudaGetSymbolAddress((void**)&Xq, g_Xq);
    cudaGetSymbolAddress((void**)&Xk, g_Xk);
    cudaGetSymbolAddress((void**)&Xv, g_Xv);
    cudaGetSymbolAddress((void**)&Qh, g_Qh);
    cudaGetSymbolAddress((void**)&Kh, g_Kh);
    cudaGetSymbolAddress((void**)&Vt, g_Vt);
    cudaGetSymbolAddress((void**)&Oh, g_Oh);
    cudaGetSymbolAddress((void**)&Ph, g_Ph);
    cudaGetSymbolAddress((void**)&Wqt, g_Wqt);
    cudaGetSymbolAddress((void**)&Wkt, g_Wkt);
    cudaGetSymbolAddress((void**)&Wvt, g_Wvt);
    cudaGetSymbolAddress((void**)&Wot, g_Wot);
    cudaGetSymbolAddress((void**)&S1, g_S1);
    cudaGetSymbolAddress((void**)&S2, g_S2);
    cudaGetSymbolAddress((void**)&Mb, g_Mb);

    cudaFuncSetAttribute((gemm_l<128, 128, 2, 4, 5, 3, 2>), cudaFuncAttributeMaxDynamicSharedMemorySize, SMEM_PRJ);
    cudaFuncSetAttribute((gemm_l<128, 128, 2, 4, 2, 2, 2>), cudaFuncAttributeMaxDynamicSharedMemorySize, SMEM_QK);
    cudaFuncSetAttribute((gemm_l<128, 256, 2, 4, 0, 4>),    cudaFuncAttributeMaxDynamicSharedMemorySize, SMEM_BIG);
    cudaFuncSetAttribute((gemm_l<128, 128, 2, 4, 4, 3, 2>), cudaFuncAttributeMaxDynamicSharedMemorySize, SMEM_PRJ);
    cudaFuncSetAttribute((gemm_l<64, 64, 4, 2, 0, 4, 3>),   cudaFuncAttributeMaxDynamicSharedMemorySize, SMEM_AV);

    // side stream + events (capture-safe fork/join, verified in R13/R15)
    cudaStream_t sB;
    cudaStreamCreateWithFlags(&sB, cudaStreamNonBlocking);
    cudaEvent_t eFork, ePrep;
    cudaEventCreateWithFlags(&eFork, cudaEventDisableTiming);
    cudaEventCreateWithFlags(&ePrep, cudaEventDisableTiming);

    dim3 blk(256);

    // fork point: sB starts at capture origin
    cudaEventRecord(eFork, 0);
    cudaStreamWaitEvent(sB, eFork, 0);

    // ---- sB: mask bitpack + P convert + Wo transpose (not needed until later) ----
    pack_k<<<(int)(((long)B_ * S_ * S_) / 256), blk, 0, sB>>>(mask, Mb);
    cvt1_k<<<(int)(((long)S_ * S_) / 1024), blk, 0, sB>>>((const float4*)prop, (uint2*)Ph);
    {
        TR tw;
        tw.in[0] = Wo; tw.out[0] = Wot;
        tw.in[1] = Wo; tw.out[1] = Wot;   // unused z<1
        tw.in[2] = Wo; tw.out[2] = Wot;
        tw.in[3] = Wo; tw.out[3] = Wot;
        tr4_k<<<dim3(D_ / 32, D_ / 32, 1), blk, 0, sB>>>(tw);
    }
    cudaEventRecord(ePrep, sB);

    // ---- s0: input converts + Q/K/V weight transposes (needed by projections) ----
    {
        CV cp;
        cp.in[0] = (const float4*)inq;  cp.out[0] = (uint2*)Xq;
        cp.in[1] = (const float4*)ink;  cp.out[1] = (uint2*)Xk;
        cp.in[2] = (const float4*)invv; cp.out[2] = (uint2*)Xv;
        cp.in[3] = (const float4*)inq;  cp.out[3] = (uint2*)Xq;   // unused z<3
        cvt3_k<<<dim3(2048, 1, 3), blk>>>(cp);
        TR tp;
        tp.in[0] = Wq; tp.out[0] = Wqt;
        tp.in[1] = Wk; tp.out[1] = Wkt;
        tp.in[2] = Wv; tp.out[2] = Wvt;
        tp.in[3] = Wq; tp.out[3] = Wqt;   // unused z<3
        tr4_k<<<dim3(D_ / 32, D_ / 32, 3), blk>>>(tp);
    }

    // 1: all three projections in one launch (z = 0:Q, 1:K, 2:V-transposed)
    //    128x128 tile, 3 stages, 2 CTAs/SM (latency-bound kernel: more CTAs win)
    {
        HP p{};
        p.lda = D_; p.ldb = D_; p.ldc = D_;
        p.K = D_;
        p.A  = Xq; p.Bm  = Wqt; p.C  = Qh; p.bias  = bq;
        p.A1 = Xk; p.Bm1 = Wkt; p.C1 = Kh; p.bias1 = bk;
        p.A2 = Xv; p.Bm2 = Wvt; p.C2 = Vt; p.bias2 = bv;
        dim3 grid(D_ / 128, (B_ * S_) / 128, 3);
        gemm_l<128, 128, 2, 4, 5, 3, 2><<<grid, blk, SMEM_PRJ>>>(p);
    }

    // join: mask bits + Ph + Wot ready before QK^T / prop / Wo
    cudaStreamWaitEvent(0, ePrep, 0);

    // 2: S1 = maskbit ? (Q.K^T)/8 : 0   (batched NT, K=64; 128x128, 2 CTAs/SM)
    {
        HP p{};
        p.A = Qh; p.lda = D_; p.Ab = (long)S_ * D_; p.Ah = DK_;
        p.Bm = Kh; p.ldb = D_; p.Bb = (long)S_ * D_; p.Bh = DK_;
        p.C = S1; p.ldc = S_; p.Cb = (long)H_ * S_ * S_; p.Ch = (long)S_ * S_;
        p.mask = Mb; p.maskB = (long)S_ * S_ / 32;
        p.scale = 0.125f;
        p.K = DK_;
        dim3 grid(S_ / 128, S_ / 128, B_ * H_);
        gemm_l<128, 128, 2, 4, 2, 2, 2><<<grid, blk, SMEM_QK>>>(p);
    }

    // 3: S2 = S1 @ P^T   (batched NT, K=2048 — tensor-roofline GEMM)
    {
        HP p{};
        p.A = S1; p.lda = S_; p.Ab = (long)H_ * S_ * S_; p.Ah = (long)S_ * S_;
        p.Bm = Ph; p.ldb = S_;
        p.C = S2; p.ldc = S_; p.Cb = (long)H_ * S_ * S_; p.Ch = (long)S_ * S_;
        p.K = S_;
        dim3 grid(S_ / 256, S_ / 128, B_ * H_);
        gemm_l<128, 256, 2, 4, 0, 4><<<grid, blk, SMEM_BIG>>>(p);
    }

    // 4: masked softmax + nan_to_num (in place, fp16, bit mask)
    softmax_h<<<B_ * H_ * S_, blk>>>(S2, Mb);

    // 5: Oh = probs @ V   (batched NT vs Vt; 64x64 tile, 3 CTAs/SM, 2.3 waves)
    {
        HP p{};
        p.A = S2; p.lda = S_; p.Ab = (long)H_ * S_ * S_; p.Ah = (long)S_ * S_;
        p.Bm = Vt; p.ldb = S_; p.Bb = (long)H_ * DK_ * S_; p.Bh = (long)DK_ * S_;
        p.C = Oh; p.ldc = D_; p.Cb = (long)S_ * D_; p.Ch = DK_;
        p.K = S_;
        dim3 grid(1, S_ / 64, B_ * H_);
        gemm_l<64, 64, 4, 2, 0, 4, 3><<<grid, blk, SMEM_AV>>>(p);
    }

    // 6: out = Oh @ Wo + bo   (NT, fp32 store; 128x128, 2 CTAs/SM)
    {
        HP p{};
        p.A = Oh; p.lda = D_;
        p.Bm = Wot; p.ldb = D_;
        p.bias = bo;
        p.C = d_out; p.ldc = D_;
        p.K = D_;
        dim3 grid(D_ / 128, (B_ * S_) / 128, 1);
        gemm_l<128, 128, 2, 4, 4, 3, 2><<<grid, blk, SMEM_PRJ>>>(p);
    }
}